// round 2
// baseline (speedup 1.0000x reference)
#include <cuda_runtime.h>

// Shapes: B=2, C=64, 4C=256, H=W=256, WS=8, hn=wn=32, P=64, DMAX=48
#define HW    65536
#define CHW4  16777216   // 256*65536
#define CHW1  4194304    // 64*65536
#define HALF_OUT 8388608 // 2*64*65536

// ------------------ device scratch (no runtime allocation) ------------------
__device__ float g_y  [2*256*65536];   // conv1 output (leaky), reused left then right
__device__ float g_Q  [2*64*65536];
__device__ float g_K  [2*64*65536];
__device__ float g_GQ [2*64*65536];    // gather_w(Q, l2r)  flat [b,y,x,c]
__device__ float g_GK [2*64*65536];    // gather_w(K, r2l)
__device__ float g_GXL[2*64*65536];    // gather_w(x_left, l2r)
__device__ float g_GXR[2*64*65536];    // gather_w(x_right, r2l)
__device__ float g_w1r[4*64*9*64];     // rb_w1 rearranged [g][ic][tap][oc]
__device__ float g_w2r[4*64*9*64];
__device__ float g_aff[4][256];        // [0]=aL [1]=bL [2]=aR [3]=bR

// ------------------ BN batch stats (per channel over B,H,W) ------------------
__global__ void bn_stats_kernel(const float* __restrict__ cat,
                                const float* __restrict__ gamma,
                                const float* __restrict__ beta, int side)
{
    int ch = blockIdx.x, tid = threadIdx.x;
    const float* p0 = cat + (size_t)ch * HW;
    const float* p1 = cat + (size_t)CHW4 + (size_t)ch * HW;
    double s = 0.0, sq = 0.0;
    for (int e = tid; e < HW; e += 256) {
        float v0 = p0[e], v1 = p1[e];
        s  += (double)v0 + (double)v1;
        sq += (double)v0 * v0 + (double)v1 * v1;
    }
    __shared__ double sh_s[256], sh_q[256];
    sh_s[tid] = s; sh_q[tid] = sq;
    __syncthreads();
    for (int st = 128; st > 0; st >>= 1) {
        if (tid < st) { sh_s[tid] += sh_s[tid+st]; sh_q[tid] += sh_q[tid+st]; }
        __syncthreads();
    }
    if (tid == 0) {
        double n = 131072.0;
        double mu  = sh_s[0] / n;
        double var = sh_q[0] / n - mu * mu;
        float a = gamma[ch] * rsqrtf((float)var + 1e-5f);
        g_aff[side*2][ch]   = a;
        g_aff[side*2+1][ch] = beta[ch] - a * (float)mu;
    }
}

// ------------------ weight rearrange [o][ic][3][3] -> [g][ic][tap][oc] ------------------
__global__ void rearrange_w_kernel(const float* __restrict__ w_in, int which)
{
    float* w_out = which ? g_w2r : g_w1r;
    int o = blockIdx.x;               // 0..255
    int g = o >> 6, oc = o & 63;
    for (int e = threadIdx.x; e < 576; e += blockDim.x) {
        int ic = e / 9, tap = e - ic * 9;
        w_out[((g*64 + ic)*9 + tap)*64 + oc] = w_in[o*576 + e];
    }
}

// ------------------ grouped 3x3 conv mainloop ------------------
struct __align__(16) ConvSmem {
    float s_in[16][10][11];      // 16 ic x (8+2) rows x (8+2)+pad cols
    float s_w [16][9][64];       // 16 ic x 9 taps x 64 oc
};
struct __align__(16) ProjSmem {
    float res[64][8][9];         // resb tile [ic][row][col(+pad)]
    float w  [16][64];           // 1x1 weights for this group
};
union __align__(16) ConvUnion { ConvSmem c; ProjSmem p; };

__device__ __forceinline__ void conv_mainloop(
    ConvSmem* sm, const float* __restrict__ in_base,
    const float* __restrict__ a_bn, const float* __restrict__ b_bn,
    const float* __restrict__ w_base,
    int h0, int w0, int tid, int r, int ocg, float acc[4][8], bool affine)
{
    for (int chunk = 0; chunk < 4; chunk++) {
        // input tile with halo, zero-padded, BN affine applied in-load
        for (int e = tid; e < 1600; e += 128) {
            int ic  = e / 100;
            int rc  = e - ic * 100;
            int row = rc / 10;
            int col = rc - row * 10;
            int hh = h0 - 1 + row, ww = w0 - 1 + col;
            float v = 0.f;
            if ((unsigned)hh < 256u && (unsigned)ww < 256u) {
                v = in_base[(size_t)(chunk*16 + ic) * HW + hh*256 + ww];
                if (affine) {
                    int ch = chunk*16 + ic;
                    v = fmaf(a_bn[ch], v, b_bn[ch]);
                }
            }
            sm->s_in[ic][row][col] = v;
        }
        // weights: contiguous 9216 floats per (group, chunk)
        {
            const float4* ws = (const float4*)(w_base + chunk*9216);
            float4* wd = (float4*)&sm->s_w[0][0][0];
            for (int e = tid; e < 2304; e += 128) wd[e] = ws[e];
        }
        __syncthreads();
        #pragma unroll 1
        for (int ic = 0; ic < 16; ic++) {
            float rin[3][10];
            #pragma unroll
            for (int dy = 0; dy < 3; dy++)
                #pragma unroll
                for (int x = 0; x < 10; x++)
                    rin[dy][x] = sm->s_in[ic][r + dy][x];
            #pragma unroll
            for (int dy = 0; dy < 3; dy++) {
                #pragma unroll
                for (int dx = 0; dx < 3; dx++) {
                    float4 wv = *(const float4*)&sm->s_w[ic][dy*3 + dx][ocg*4];
                    #pragma unroll
                    for (int cc = 0; cc < 8; cc++) {
                        float xv = rin[dy][cc + dx];
                        acc[0][cc] = fmaf(wv.x, xv, acc[0][cc]);
                        acc[1][cc] = fmaf(wv.y, xv, acc[1][cc]);
                        acc[2][cc] = fmaf(wv.z, xv, acc[2][cc]);
                        acc[3][cc] = fmaf(wv.w, xv, acc[3][cc]);
                    }
                }
            }
        }
        __syncthreads();
    }
}

// ------------------ conv1: y = leaky( conv3x3(bn(cat)) + b1 ) ------------------
__global__ __launch_bounds__(128) void conv1_kernel(
    const float* __restrict__ cat, const float* __restrict__ b1, int side)
{
    __shared__ ConvSmem sm;
    int tile = blockIdx.x, g = blockIdx.y, b = blockIdx.z;
    int h0 = (tile >> 5) * 8, w0 = (tile & 31) * 8;
    int tid = threadIdx.x, r = tid & 7, ocg = tid >> 3;
    float acc[4][8];
    #pragma unroll
    for (int u = 0; u < 4; u++)
        #pragma unroll
        for (int cc = 0; cc < 8; cc++) acc[u][cc] = 0.f;

    const float* in_base = cat + (size_t)b*CHW4 + (size_t)(g*64)*HW;
    conv_mainloop(&sm, in_base, &g_aff[side*2][g*64], &g_aff[side*2+1][g*64],
                  g_w1r + g*36864, h0, w0, tid, r, ocg, acc, true);

    float* ob = g_y + (size_t)b*CHW4 + (size_t)(g*64)*HW + (size_t)(h0 + r)*256 + w0;
    #pragma unroll
    for (int u = 0; u < 4; u++) {
        int oc = ocg*4 + u;
        float bv = b1[g*64 + oc];
        float* op = ob + (size_t)oc * HW;
        #pragma unroll
        for (int cc = 0; cc < 8; cc++) {
            float v = acc[u][cc] + bv;
            op[cc] = (v > 0.f) ? v : 0.1f * v;
        }
    }
}

// ------------------ conv2 + residual + grouped 1x1 projection ------------------
__global__ __launch_bounds__(128) void conv2proj_kernel(
    const float* __restrict__ cat, const float* __restrict__ b2,
    const float* __restrict__ pw, const float* __restrict__ pb, int side)
{
    __shared__ ConvUnion sm;
    int tile = blockIdx.x, g = blockIdx.y, b = blockIdx.z;
    int h0 = (tile >> 5) * 8, w0 = (tile & 31) * 8;
    int tid = threadIdx.x, r = tid & 7, ocg = tid >> 3;
    float acc[4][8];
    #pragma unroll
    for (int u = 0; u < 4; u++)
        #pragma unroll
        for (int cc = 0; cc < 8; cc++) acc[u][cc] = 0.f;

    const float* in_base = g_y + (size_t)b*CHW4 + (size_t)(g*64)*HW;
    conv_mainloop(&sm.c, in_base, nullptr, nullptr,
                  g_w2r + g*36864, h0, w0, tid, r, ocg, acc, false);

    // resb = conv2 + b2 + bn(cat); store tile to smem for the 1x1 projection
    const float* a_bn = &g_aff[side*2][g*64];
    const float* b_bn = &g_aff[side*2+1][g*64];
    const float* catb = cat + (size_t)b*CHW4 + (size_t)(g*64)*HW + (size_t)(h0 + r)*256 + w0;
    #pragma unroll
    for (int u = 0; u < 4; u++) {
        int oc = ocg*4 + u;
        float bv = b2[g*64 + oc];
        float av = a_bn[oc], bb = b_bn[oc];
        const float* cp = catb + (size_t)oc * HW;
        #pragma unroll
        for (int cc = 0; cc < 8; cc++)
            sm.p.res[oc][r][cc] = acc[u][cc] + bv + fmaf(av, cp[cc], bb);
    }
    for (int e = tid; e < 1024; e += 128) {
        int o16 = e >> 6, ic = e & 63;
        sm.p.w[o16][ic] = pw[(g*16 + o16)*64 + ic];
    }
    __syncthreads();

    int o16 = tid >> 3, rr = tid & 7;
    float accp[8];
    float pbv = pb[g*16 + o16];
    #pragma unroll
    for (int cc = 0; cc < 8; cc++) accp[cc] = pbv;
    #pragma unroll 1
    for (int ic = 0; ic < 64; ic++) {
        float wv = sm.p.w[o16][ic];
        #pragma unroll
        for (int cc = 0; cc < 8; cc++)
            accp[cc] = fmaf(wv, sm.p.res[ic][rr][cc], accp[cc]);
    }
    float* qout = (side == 0) ? g_Q : g_K;
    float* op = qout + (size_t)b*CHW1 + (size_t)(g*16 + o16)*HW + (size_t)(h0 + rr)*256 + w0;
    #pragma unroll
    for (int cc = 0; cc < 8; cc++) op[cc] = accp[cc];
}

// ------------------ transpose-gather: [b,c,h,w] + idx -> flat [b,y,x,c] ------------------
// mode 0: src_col = min(x + d, 255) (l2r, d_right); mode 1: src_col = max(x - d, 0) (r2l, d_left)
__global__ __launch_bounds__(256) void gather_kernel(
    const float* __restrict__ srcParam, const int* __restrict__ dvals,
    int mode, int srcSel, int dstSel)
{
    __shared__ float s[64][113];
    int x0 = blockIdx.x * 64;
    int y  = blockIdx.y;
    int b  = blockIdx.z;
    const float* src = (srcSel == 0) ? g_Q : (srcSel == 1) ? g_K : srcParam;
    float* dst = (dstSel == 0) ? g_GQ : (dstSel == 1) ? g_GK :
                 (dstSel == 2) ? g_GXR : g_GXL;
    int lo = (mode == 0) ? x0 : max(x0 - 48, 0);
    int t = threadIdx.x;
    const float* sb = src + (size_t)b*CHW1 + y*256;
    for (int e = t; e < 64*112; e += 256) {
        int c = e / 112, j = e - c*112;
        int col = min(lo + j, 255);
        s[c][j] = sb[(size_t)c*HW + col];
    }
    __syncthreads();
    float* db = dst + (size_t)b*CHW1 + y*16384 + x0*64;
    const int* dp = dvals + b*HW + y*256;
    for (int e = t; e < 4096; e += 256) {
        int xi = e >> 6, c = e & 63;
        int x = x0 + xi;
        int d = dp[x];
        int sc = (mode == 0) ? min(x + d, 255) : max(x - d, 0);
        db[xi*64 + c] = s[c][sc - lo];
    }
}

// ------------------ per-window attention + output assembly ------------------
__global__ __launch_bounds__(256) void attn_kernel(
    const float* __restrict__ xl, const float* __restrict__ xr,
    const int* __restrict__ dl, const int* __restrict__ dr,
    float* __restrict__ out)
{
    __shared__ __align__(16) float sA[64][68];
    __shared__ __align__(16) float sB[64][68];
    __shared__ float mu[8];
    int win = blockIdx.x, side = blockIdx.y, b = blockIdx.z;
    int hi = win >> 5, wi = win & 31;
    int t = threadIdx.x;

    const float *Ab, *Bb, *Xb;
    if (side == 0) { Ab = g_Q; Bb = g_GK; Xb = g_GXR; }
    else           { Ab = g_K; Bb = g_GQ; Xb = g_GXL; }
    size_t base = (size_t)b*CHW1 + (size_t)(hi*8)*256 + wi*8;

    // load A (patch of real tensor) and B (fake patch of gathered flat) — same formula
    for (int e = t; e < 4096; e += 256) {
        int j = e & 63, c = e >> 6;
        size_t off = base + (size_t)c*HW + (j >> 3)*256 + (j & 7);
        sA[j][c] = Ab[off];
        sB[j][c] = Bb[off];
    }
    __syncthreads();

    // mu[p] = mean over (q, c) of B rows p*8..p*8+7  (reference's mean((4,5)))
    {
        int w = t >> 5, lane = t & 31;
        float s = 0.f;
        int row = w*8 + (lane >> 2);
        int c0  = (lane & 3) * 16;
        #pragma unroll
        for (int m = 0; m < 16; m++) s += sB[row][c0 + m];
        #pragma unroll
        for (int o = 16; o; o >>= 1) s += __shfl_xor_sync(0xffffffffu, s, o);
        if (lane == 0) mu[w] = s * (1.f/512.f);
    }
    __syncthreads();
    {
        int j = t >> 2, cb = t & 3;
        float m = mu[j >> 3];
        #pragma unroll
        for (int k = 0; k < 16; k++) sB[j][cb + 4*k] -= m;
    }
    __syncthreads();

    // scores: thread owns row i = t>>2, 16 j's strided by 4
    int i = t >> 2, jq = t & 3;
    float S[16];
    #pragma unroll
    for (int k = 0; k < 16; k++) S[k] = 0.f;
    #pragma unroll 4
    for (int c4 = 0; c4 < 16; c4++) {
        float4 a4 = *(const float4*)&sA[i][c4*4];
        #pragma unroll
        for (int k = 0; k < 16; k++) {
            float4 b4 = *(const float4*)&sB[jq + 4*k][c4*4];
            S[k] = fmaf(a4.x, b4.x, S[k]);
            S[k] = fmaf(a4.y, b4.y, S[k]);
            S[k] = fmaf(a4.z, b4.z, S[k]);
            S[k] = fmaf(a4.w, b4.w, S[k]);
        }
    }
    // softmax over j (row split across the quad)
    float mx = S[0];
    #pragma unroll
    for (int k = 1; k < 16; k++) mx = fmaxf(mx, S[k]);
    mx = fmaxf(mx, __shfl_xor_sync(0xffffffffu, mx, 1));
    mx = fmaxf(mx, __shfl_xor_sync(0xffffffffu, mx, 2));
    float sum = 0.f;
    #pragma unroll
    for (int k = 0; k < 16; k++) { S[k] = __expf(S[k] - mx); sum += S[k]; }
    sum += __shfl_xor_sync(0xffffffffu, sum, 1);
    sum += __shfl_xor_sync(0xffffffffu, sum, 2);
    float inv = 1.f / sum;

    __syncthreads();                    // done reading sA/sB for scores
    #pragma unroll
    for (int k = 0; k < 16; k++) sA[i][jq + 4*k] = S[k] * inv;   // M -> sA
    for (int e = t; e < 4096; e += 256) {                        // X -> sB
        int j = e & 63, c = e >> 6;
        sB[j][c] = Xb[base + (size_t)c*HW + (j >> 3)*256 + (j & 7)];
    }
    __syncthreads();

    // apply: O[i][c] = sum_j M[i][j] * X[j][c]; thread covers c4 = jq + 4k
    float4 acc[4];
    #pragma unroll
    for (int k = 0; k < 4; k++) acc[k] = make_float4(0.f, 0.f, 0.f, 0.f);
    #pragma unroll 4
    for (int j = 0; j < 64; j++) {
        float m = sA[i][j];
        #pragma unroll
        for (int k = 0; k < 4; k++) {
            float4 x4 = *(const float4*)&sB[j][(jq + 4*k)*4];
            acc[k].x = fmaf(m, x4.x, acc[k].x);
            acc[k].y = fmaf(m, x4.y, acc[k].y);
            acc[k].z = fmaf(m, x4.z, acc[k].z);
            acc[k].w = fmaf(m, x4.w, acc[k].w);
        }
    }

    // output: out = x + O * mask
    int p = i >> 3, q = i & 7;
    int Y = hi*8 + p, Xw = wi*8 + q;
    const float* xbase;
    float mval;
    if (side == 0) {
        xbase = xl;
        int d = dl[b*HW + Y*256 + Xw];
        mval = (Xw - d >= 0) ? 1.f : 0.f;
    } else {
        xbase = xr;
        int d = dr[b*HW + Y*256 + Xw];
        mval = (Xw + d <= 255) ? 1.f : 0.f;
    }
    float* op = out + (size_t)side*HALF_OUT + (size_t)b*CHW1 + Y*256 + Xw;
    const float* xp = xbase + (size_t)b*CHW1 + Y*256 + Xw;
    #pragma unroll
    for (int k = 0; k < 4; k++) {
        int cb = (jq + 4*k) * 4;
        float vals[4] = {acc[k].x, acc[k].y, acc[k].z, acc[k].w};
        #pragma unroll
        for (int e = 0; e < 4; e++) {
            size_t go = (size_t)(cb + e) * HW;
            op[go] = xp[go] + vals[e] * mval;
        }
    }
}

// ------------------ launch ------------------
extern "C" void kernel_launch(void* const* d_in, const int* in_sizes, int n_in,
                              void* d_out, int out_size)
{
    (void)in_sizes; (void)n_in; (void)out_size;
    const float* x_left  = (const float*)d_in[0];
    const float* x_right = (const float*)d_in[1];
    const float* cat_l   = (const float*)d_in[2];
    const float* cat_r   = (const float*)d_in[3];
    const int*   d_left  = (const int*)d_in[4];
    const int*   d_right = (const int*)d_in[5];
    const float* gamma   = (const float*)d_in[6];
    const float* beta    = (const float*)d_in[7];
    const float* rb_w1   = (const float*)d_in[8];
    const float* rb_b1   = (const float*)d_in[9];
    const float* rb_w2   = (const float*)d_in[10];
    const float* rb_b2   = (const float*)d_in[11];
    const float* bq_w    = (const float*)d_in[12];
    const float* bq_b    = (const float*)d_in[13];
    const float* bs_w    = (const float*)d_in[14];
    const float* bs_b    = (const float*)d_in[15];
    float* out = (float*)d_out;

    bn_stats_kernel<<<256, 256>>>(cat_l, gamma, beta, 0);
    bn_stats_kernel<<<256, 256>>>(cat_r, gamma, beta, 1);
    rearrange_w_kernel<<<256, 128>>>(rb_w1, 0);
    rearrange_w_kernel<<<256, 128>>>(rb_w2, 1);

    dim3 cgrid(1024, 4, 2);
    conv1_kernel   <<<cgrid, 128>>>(cat_l, rb_b1, 0);
    conv2proj_kernel<<<cgrid, 128>>>(cat_l, rb_b2, bq_w, bq_b, 0);   // -> g_Q
    conv1_kernel   <<<cgrid, 128>>>(cat_r, rb_b1, 1);                // g_y reused (stream-ordered)
    conv2proj_kernel<<<cgrid, 128>>>(cat_r, rb_b2, bs_w, bs_b, 1);   // -> g_K

    dim3 ggrid(4, 256, 2);
    gather_kernel<<<ggrid, 256>>>(nullptr, d_right, 0, 0, 0);  // G_Q  = gather(Q, l2r)
    gather_kernel<<<ggrid, 256>>>(nullptr, d_left,  1, 1, 1);  // G_K  = gather(K, r2l)
    gather_kernel<<<ggrid, 256>>>(x_right, d_left,  1, 2, 2);  // G_XR = gather(x_right, r2l)
    gather_kernel<<<ggrid, 256>>>(x_left,  d_right, 0, 2, 3);  // G_XL = gather(x_left, l2r)

    attn_kernel<<<dim3(1024, 2, 2), 256>>>(x_left, x_right, d_left, d_right, out);
}

// round 3
// speedup vs baseline: 1.5698x; 1.5698x over previous
#include <cuda_runtime.h>

// Shapes: B=2, C=64, 4C=256, H=W=256, WS=8, hn=wn=32, P=64, DMAX=48
#define HW    65536
#define CHW4  16777216   // 256*65536
#define CHW1  4194304    // 64*65536
#define HALF_OUT 8388608 // 2*64*65536

// ------------------ device scratch (no runtime allocation) ------------------
__device__ float g_y  [2*256*65536];   // conv1 output (leaky), reused left then right
__device__ float g_Q  [2*64*65536];
__device__ float g_K  [2*64*65536];
__device__ float g_GQ [2*64*65536];    // gather_w(Q, l2r)  flat [b,y,x,c]
__device__ float g_GK [2*64*65536];    // gather_w(K, r2l)
__device__ float g_GXL[2*64*65536];    // gather_w(x_left, l2r)
__device__ float g_GXR[2*64*65536];    // gather_w(x_right, r2l)
__device__ float g_w1m[4*8*9*64*8];    // rb_w1 as [g][chunk][tap][oc][c4][sub2], tf32-rounded
__device__ float g_w2m[4*8*9*64*8];
__device__ float g_aff[4][256];        // [0]=aL [1]=bL [2]=aR [3]=bR

__device__ __forceinline__ unsigned f2tf(float f) {
    unsigned u; asm("cvt.rna.tf32.f32 %0, %1;" : "=r"(u) : "f"(f)); return u;
}

#define MMA_TF32(d, A, b0, b1)                                              \
    asm volatile("mma.sync.aligned.m16n8k8.row.col.f32.tf32.tf32.f32 "      \
        "{%0,%1,%2,%3}, {%4,%5,%6,%7}, {%8,%9}, {%0,%1,%2,%3};"             \
        : "+f"(d[0]), "+f"(d[1]), "+f"(d[2]), "+f"(d[3])                    \
        : "r"(A[0]), "r"(A[1]), "r"(A[2]), "r"(A[3]), "r"(b0), "r"(b1))

// ------------------ BN batch stats (per channel over B,H,W) ------------------
__global__ void bn_stats_kernel(const float* __restrict__ cat,
                                const float* __restrict__ gamma,
                                const float* __restrict__ beta, int side)
{
    int ch = blockIdx.x, tid = threadIdx.x;
    const float* p0 = cat + (size_t)ch * HW;
    const float* p1 = cat + (size_t)CHW4 + (size_t)ch * HW;
    double s = 0.0, sq = 0.0;
    for (int e = tid; e < HW; e += 256) {
        float v0 = p0[e], v1 = p1[e];
        s  += (double)v0 + (double)v1;
        sq += (double)v0 * v0 + (double)v1 * v1;
    }
    __shared__ double sh_s[256], sh_q[256];
    sh_s[tid] = s; sh_q[tid] = sq;
    __syncthreads();
    for (int st = 128; st > 0; st >>= 1) {
        if (tid < st) { sh_s[tid] += sh_s[tid+st]; sh_q[tid] += sh_q[tid+st]; }
        __syncthreads();
    }
    if (tid == 0) {
        double n = 131072.0;
        double mu  = sh_s[0] / n;
        double var = sh_q[0] / n - mu * mu;
        float a = gamma[ch] * rsqrtf((float)var + 1e-5f);
        g_aff[side*2][ch]   = a;
        g_aff[side*2+1][ch] = beta[ch] - a * (float)mu;
    }
}

// ------------------ weight rearrange [o][ic][3][3] -> [g][chunk][tap][oc][c][sub] tf32 ------------------
__global__ void rearrange_w_kernel(const float* __restrict__ w_in, int which)
{
    float* wo = which ? g_w2m : g_w1m;
    int o = blockIdx.x;               // 0..255
    int g = o >> 6, oc = o & 63;
    for (int e = threadIdx.x; e < 576; e += blockDim.x) {
        int ic = e / 9, t = e - ic * 9;
        int ch = ic >> 3, icc = ic & 7;
        int c = icc & 3, sub = icc >> 2;      // ic = chunk*8 + c + 4*sub
        float v = w_in[o*576 + e];
        wo[((((g*8 + ch)*9 + t)*64 + oc)*4 + c)*2 + sub] = __uint_as_float(f2tf(v));
    }
}

// ------------------ tensor-core conv smem layouts ------------------
struct __align__(16) ConvTCSmem {
    unsigned in[4*130*8];    // [plane4][col130][slot8] tf32 bits; slot s: ic=(s>>1)+4*(s&1)
    float    w [4608];       // [tap9][oc64][c4][sub2] tf32-rounded (straight copy)
};
struct __align__(16) Proj2Smem {
    float resb[64*136];      // [ch64][px128 pitch136]
    float pw  [1024];        // [o16][kk8][c4][sub2] tf32-rounded
};
union __align__(16) TCUnion { ConvTCSmem c; Proj2Smem p; };

// Tile: 2 image rows (y0, y0+1) x 128 cols (x0..x0+127). 8 warps; warp w:
// row = w>>2, x-slice = (w&3)*32. Per warp: 64 oc (4 mfrags) x 32 px (4 nfrags).
__device__ __forceinline__ void conv_mma_loop(
    ConvTCSmem* sm, const float* __restrict__ in_base,
    const float* __restrict__ wm_base,
    const float* __restrict__ a_bn, const float* __restrict__ b_bn, bool affine,
    int y0, int x0, int tid, float acc[4][4][4])
{
    int lane = tid & 31, warp = tid >> 5;
    int wrow = warp >> 2, wx = (warp & 3) * 32;
    int r4 = lane >> 2, c4 = lane & 3;

    #pragma unroll 1
    for (int chunk = 0; chunk < 8; chunk++) {
        // stage input halo: planes y0-1..y0+2, cols x0-1..x0+128, 8 ic (tf32)
        for (int e = tid; e < 4160; e += 256) {
            int s   = e / 520;
            int rem = e - s * 520;
            int pl  = rem / 130, col = rem - pl * 130;
            int ic  = chunk*8 + (s >> 1) + 4*(s & 1);
            int yy = y0 + pl - 1, xx = x0 + col - 1;
            float v = 0.f;
            if ((unsigned)yy < 256u && (unsigned)xx < 256u) {
                v = in_base[(size_t)ic * HW + yy*256 + xx];
                if (affine) v = fmaf(a_bn[ic], v, b_bn[ic]);
            }
            sm->in[(pl*130 + col)*8 + s] = f2tf(v);
        }
        // stage weights: straight float4 copy (already tf32 + in frag layout)
        {
            const float4* wsrc = (const float4*)(wm_base + chunk*4608);
            float4* wd = (float4*)sm->w;
            for (int e = tid; e < 1152; e += 256) wd[e] = wsrc[e];
        }
        __syncthreads();

        #pragma unroll
        for (int tap = 0; tap < 9; tap++) {
            const int dy = tap / 3, dx = tap - dy*3;
            // A frags = weights [64oc x 8ic]
            const unsigned* wS = (const unsigned*)sm->w + tap*512;
            unsigned A[4][4];
            #pragma unroll
            for (int mf = 0; mf < 4; mf++) {
                int oc0 = mf*16 + r4;
                uint2 p0 = *(const uint2*)(wS + oc0*8       + c4*2);
                uint2 p1 = *(const uint2*)(wS + (oc0+8)*8   + c4*2);
                A[mf][0] = p0.x; A[mf][1] = p1.x; A[mf][2] = p0.y; A[mf][3] = p1.y;
            }
            // B frags = input [8ic x 8px]
            const unsigned* bp = sm->in + ((wrow + dy)*130 + wx + dx + r4)*8 + c4*2;
            #pragma unroll
            for (int nf = 0; nf < 4; nf++) {
                uint2 bb = *(const uint2*)(bp + nf*64);
                #pragma unroll
                for (int mf = 0; mf < 4; mf++)
                    MMA_TF32(acc[mf][nf], A[mf], bb.x, bb.y);
            }
        }
        __syncthreads();
    }
}

// ------------------ conv1: g_y = leaky( conv3x3(bn(cat)) + b1 ) ------------------
__global__ __launch_bounds__(256, 2) void conv1_kernel(
    const float* __restrict__ cat, const float* __restrict__ b1, int side)
{
    __shared__ ConvTCSmem sm;
    int tile = blockIdx.x, g = blockIdx.y, b = blockIdx.z;
    int x0 = (tile & 1) * 128, y0 = (tile >> 1) * 2;
    int tid = threadIdx.x, lane = tid & 31, warp = tid >> 5;
    int wrow = warp >> 2, wx = (warp & 3) * 32;
    int r4 = lane >> 2, c4 = lane & 3;

    float acc[4][4][4];
    #pragma unroll
    for (int m = 0; m < 4; m++)
        #pragma unroll
        for (int n = 0; n < 4; n++)
            #pragma unroll
            for (int k = 0; k < 4; k++) acc[m][n][k] = 0.f;

    const float* in_base = cat + (size_t)b*CHW4 + (size_t)(g*64)*HW;
    conv_mma_loop(&sm, in_base, g_w1m + g*36864,
                  &g_aff[side*2][g*64], &g_aff[side*2+1][g*64], true,
                  y0, x0, tid, acc);

    const float* b1g = b1 + g*64;
    float* ob = g_y + (size_t)b*CHW4 + (size_t)(g*64)*HW + (size_t)(y0 + wrow)*256 + x0 + wx;
    #pragma unroll
    for (int mf = 0; mf < 4; mf++) {
        int oc = mf*16 + r4;
        float bv0 = b1g[oc], bv1 = b1g[oc + 8];
        #pragma unroll
        for (int nf = 0; nf < 4; nf++) {
            int xx = nf*8 + 2*c4;
            float v0 = acc[mf][nf][0] + bv0, v1 = acc[mf][nf][1] + bv0;
            float v2 = acc[mf][nf][2] + bv1, v3 = acc[mf][nf][3] + bv1;
            v0 = (v0 > 0.f) ? v0 : 0.1f*v0;  v1 = (v1 > 0.f) ? v1 : 0.1f*v1;
            v2 = (v2 > 0.f) ? v2 : 0.1f*v2;  v3 = (v3 > 0.f) ? v3 : 0.1f*v3;
            *(float2*)(ob + (size_t)oc*HW + xx)     = make_float2(v0, v1);
            *(float2*)(ob + (size_t)(oc+8)*HW + xx) = make_float2(v2, v3);
        }
    }
}

// ------------------ conv2 + residual + grouped 1x1 projection ------------------
__global__ __launch_bounds__(256, 2) void conv2proj_kernel(
    const float* __restrict__ cat, const float* __restrict__ b2,
    const float* __restrict__ pw, const float* __restrict__ pb, int side)
{
    __shared__ TCUnion sm;
    int tile = blockIdx.x, g = blockIdx.y, b = blockIdx.z;
    int x0 = (tile & 1) * 128, y0 = (tile >> 1) * 2;
    int tid = threadIdx.x, lane = tid & 31, warp = tid >> 5;
    int wrow = warp >> 2, wx = (warp & 3) * 32;
    int r4 = lane >> 2, c4 = lane & 3;

    float acc[4][4][4];
    #pragma unroll
    for (int m = 0; m < 4; m++)
        #pragma unroll
        for (int n = 0; n < 4; n++)
            #pragma unroll
            for (int k = 0; k < 4; k++) acc[m][n][k] = 0.f;

    const float* in_base = g_y + (size_t)b*CHW4 + (size_t)(g*64)*HW;
    conv_mma_loop(&sm.c, in_base, g_w2m + g*36864, nullptr, nullptr, false,
                  y0, x0, tid, acc);

    // stage 1x1 projection weights (tf32) — safe: mainloop ended with syncthreads
    for (int e = tid; e < 1024; e += 256) {
        int o = e >> 6, t6 = e & 63;
        int kk = t6 >> 3, cc = (t6 >> 1) & 3, sub = t6 & 1;
        int ic = kk*8 + cc + 4*sub;
        sm.p.pw[e] = __uint_as_float(f2tf(pw[(g*16 + o)*64 + ic]));
    }

    const float* a_bn = &g_aff[side*2][g*64];
    const float* b_bn = &g_aff[side*2+1][g*64];
    const float* b2g = b2 + g*64;
    const float* pbg = pb + g*16;
    float* qout = ((side == 0) ? g_Q : g_K) + (size_t)b*CHW1 + (size_t)(g*16)*HW;

    #pragma unroll 1
    for (int h2 = 0; h2 < 2; h2++) {
        __syncthreads();
        // warps owning this image row write resb = conv2 + b2
        if (wrow == h2) {
            int xs = (warp & 3) * 32;
            #pragma unroll
            for (int mf = 0; mf < 4; mf++) {
                int oc = mf*16 + r4;
                float bv0 = b2g[oc], bv1 = b2g[oc + 8];
                #pragma unroll
                for (int nf = 0; nf < 4; nf++) {
                    int xx = xs + nf*8 + 2*c4;
                    *(float2*)&sm.p.resb[oc*136 + xx] =
                        make_float2(acc[mf][nf][0] + bv0, acc[mf][nf][1] + bv0);
                    *(float2*)&sm.p.resb[(oc+8)*136 + xx] =
                        make_float2(acc[mf][nf][2] + bv1, acc[mf][nf][3] + bv1);
                }
            }
        }
        __syncthreads();
        // residual: resb += bn(cat); then round to tf32
        {
            const float* catb = cat + (size_t)b*CHW4 + (size_t)(g*64)*HW
                              + (size_t)(y0 + h2)*256 + x0;
            for (int e = tid; e < 8192; e += 256) {
                int chv = e >> 7, xx = e & 127;
                float v = sm.p.resb[chv*136 + xx]
                        + fmaf(a_bn[chv], catb[(size_t)chv*HW + xx], b_bn[chv]);
                sm.p.resb[chv*136 + xx] = __uint_as_float(f2tf(v));
            }
        }
        __syncthreads();
        // projection: D[128px, 16oc] = resb[128px,64] x pw^T ; warp w owns 16 px
        {
            int pxb = warp * 16;
            float dacc[2][4];
            #pragma unroll
            for (int n = 0; n < 2; n++)
                #pragma unroll
                for (int k = 0; k < 4; k++) dacc[n][k] = 0.f;
            #pragma unroll
            for (int kk = 0; kk < 8; kk++) {
                unsigned A[4];
                int ch0 = kk*8 + c4;
                A[0] = __float_as_uint(sm.p.resb[ch0*136     + pxb + r4]);
                A[1] = __float_as_uint(sm.p.resb[ch0*136     + pxb + r4 + 8]);
                A[2] = __float_as_uint(sm.p.resb[(ch0+4)*136 + pxb + r4]);
                A[3] = __float_as_uint(sm.p.resb[(ch0+4)*136 + pxb + r4 + 8]);
                #pragma unroll
                for (int nf = 0; nf < 2; nf++) {
                    uint2 bb = *(const uint2*)((const unsigned*)sm.p.pw
                                + (nf*8 + r4)*64 + kk*8 + c4*2);
                    MMA_TF32(dacc[nf], A, bb.x, bb.y);
                }
            }
            float* qb = qout + (size_t)(y0 + h2)*256 + x0;
            #pragma unroll
            for (int nf = 0; nf < 2; nf++) {
                int oc = nf*8 + 2*c4;
                int px = pxb + r4;
                float p0 = pbg[oc], p1 = pbg[oc + 1];
                qb[(size_t)oc*HW     + px]     = dacc[nf][0] + p0;
                qb[(size_t)(oc+1)*HW + px]     = dacc[nf][1] + p1;
                qb[(size_t)oc*HW     + px + 8] = dacc[nf][2] + p0;
                qb[(size_t)(oc+1)*HW + px + 8] = dacc[nf][3] + p1;
            }
        }
    }
}

// ------------------ transpose-gather: [b,c,h,w] + idx -> flat [b,y,x,c] ------------------
__global__ __launch_bounds__(256) void gather_kernel(
    const float* __restrict__ srcParam, const int* __restrict__ dvals,
    int mode, int srcSel, int dstSel)
{
    __shared__ float s[64][113];
    int x0 = blockIdx.x * 64;
    int y  = blockIdx.y;
    int b  = blockIdx.z;
    const float* src = (srcSel == 0) ? g_Q : (srcSel == 1) ? g_K : srcParam;
    float* dst = (dstSel == 0) ? g_GQ : (dstSel == 1) ? g_GK :
                 (dstSel == 2) ? g_GXR : g_GXL;
    int lo = (mode == 0) ? x0 : max(x0 - 48, 0);
    int t = threadIdx.x;
    const float* sb = src + (size_t)b*CHW1 + y*256;
    for (int e = t; e < 64*112; e += 256) {
        int c = e / 112, j = e - c*112;
        int col = min(lo + j, 255);
        s[c][j] = sb[(size_t)c*HW + col];
    }
    __syncthreads();
    float* db = dst + (size_t)b*CHW1 + y*16384 + x0*64;
    const int* dp = dvals + b*HW + y*256;
    for (int e = t; e < 4096; e += 256) {
        int xi = e >> 6, c = e & 63;
        int x = x0 + xi;
        int d = dp[x];
        int sc = (mode == 0) ? min(x + d, 255) : max(x - d, 0);
        db[xi*64 + c] = s[c][sc - lo];
    }
}

// ------------------ per-window attention + output assembly ------------------
__global__ __launch_bounds__(256) void attn_kernel(
    const float* __restrict__ xl, const float* __restrict__ xr,
    const int* __restrict__ dl, const int* __restrict__ dr,
    float* __restrict__ out)
{
    __shared__ __align__(16) float sA[64][68];
    __shared__ __align__(16) float sB[64][68];
    __shared__ float mu[8];
    int win = blockIdx.x, side = blockIdx.y, b = blockIdx.z;
    int hi = win >> 5, wi = win & 31;
    int t = threadIdx.x;

    const float *Ab, *Bb, *Xb;
    if (side == 0) { Ab = g_Q; Bb = g_GK; Xb = g_GXR; }
    else           { Ab = g_K; Bb = g_GQ; Xb = g_GXL; }
    size_t base = (size_t)b*CHW1 + (size_t)(hi*8)*256 + wi*8;

    for (int e = t; e < 4096; e += 256) {
        int j = e & 63, c = e >> 6;
        size_t off = base + (size_t)c*HW + (j >> 3)*256 + (j & 7);
        sA[j][c] = Ab[off];
        sB[j][c] = Bb[off];
    }
    __syncthreads();

    {
        int w = t >> 5, lane = t & 31;
        float s = 0.f;
        int row = w*8 + (lane >> 2);
        int c0  = (lane & 3) * 16;
        #pragma unroll
        for (int m = 0; m < 16; m++) s += sB[row][c0 + m];
        #pragma unroll
        for (int o = 16; o; o >>= 1) s += __shfl_xor_sync(0xffffffffu, s, o);
        if (lane == 0) mu[w] = s * (1.f/512.f);
    }
    __syncthreads();
    {
        int j = t >> 2, cb = t & 3;
        float m = mu[j >> 3];
        #pragma unroll
        for (int k = 0; k < 16; k++) sB[j][cb + 4*k] -= m;
    }
    __syncthreads();

    int i = t >> 2, jq = t & 3;
    float S[16];
    #pragma unroll
    for (int k = 0; k < 16; k++) S[k] = 0.f;
    #pragma unroll 4
    for (int c4 = 0; c4 < 16; c4++) {
        float4 a4 = *(const float4*)&sA[i][c4*4];
        #pragma unroll
        for (int k = 0; k < 16; k++) {
            float4 b4 = *(const float4*)&sB[jq + 4*k][c4*4];
            S[k] = fmaf(a4.x, b4.x, S[k]);
            S[k] = fmaf(a4.y, b4.y, S[k]);
            S[k] = fmaf(a4.z, b4.z, S[k]);
            S[k] = fmaf(a4.w, b4.w, S[k]);
        }
    }
    float mx = S[0];
    #pragma unroll
    for (int k = 1; k < 16; k++) mx = fmaxf(mx, S[k]);
    mx = fmaxf(mx, __shfl_xor_sync(0xffffffffu, mx, 1));
    mx = fmaxf(mx, __shfl_xor_sync(0xffffffffu, mx, 2));
    float sum = 0.f;
    #pragma unroll
    for (int k = 0; k < 16; k++) { S[k] = __expf(S[k] - mx); sum += S[k]; }
    sum += __shfl_xor_sync(0xffffffffu, sum, 1);
    sum += __shfl_xor_sync(0xffffffffu, sum, 2);
    float inv = 1.f / sum;

    __syncthreads();
    #pragma unroll
    for (int k = 0; k < 16; k++) sA[i][jq + 4*k] = S[k] * inv;
    for (int e = t; e < 4096; e += 256) {
        int j = e & 63, c = e >> 6;
        sB[j][c] = Xb[base + (size_t)c*HW + (j >> 3)*256 + (j & 7)];
    }
    __syncthreads();

    float4 acc[4];
    #pragma unroll
    for (int k = 0; k < 4; k++) acc[k] = make_float4(0.f, 0.f, 0.f, 0.f);
    #pragma unroll 4
    for (int j = 0; j < 64; j++) {
        float m = sA[i][j];
        #pragma unroll
        for (int k = 0; k < 4; k++) {
            float4 x4 = *(const float4*)&sB[j][(jq + 4*k)*4];
            acc[k].x = fmaf(m, x4.x, acc[k].x);
            acc[k].y = fmaf(m, x4.y, acc[k].y);
            acc[k].z = fmaf(m, x4.z, acc[k].z);
            acc[k].w = fmaf(m, x4.w, acc[k].w);
        }
    }

    int p = i >> 3, q = i & 7;
    int Y = hi*8 + p, Xw = wi*8 + q;
    const float* xbase;
    float mval;
    if (side == 0) {
        xbase = xl;
        int d = dl[b*HW + Y*256 + Xw];
        mval = (Xw - d >= 0) ? 1.f : 0.f;
    } else {
        xbase = xr;
        int d = dr[b*HW + Y*256 + Xw];
        mval = (Xw + d <= 255) ? 1.f : 0.f;
    }
    float* op = out + (size_t)side*HALF_OUT + (size_t)b*CHW1 + Y*256 + Xw;
    const float* xp = xbase + (size_t)b*CHW1 + Y*256 + Xw;
    #pragma unroll
    for (int k = 0; k < 4; k++) {
        int cb = (jq + 4*k) * 4;
        float vals[4] = {acc[k].x, acc[k].y, acc[k].z, acc[k].w};
        #pragma unroll
        for (int e = 0; e < 4; e++) {
            size_t go = (size_t)(cb + e) * HW;
            op[go] = xp[go] + vals[e] * mval;
        }
    }
}

// ------------------ launch ------------------
extern "C" void kernel_launch(void* const* d_in, const int* in_sizes, int n_in,
                              void* d_out, int out_size)
{
    (void)in_sizes; (void)n_in; (void)out_size;
    const float* x_left  = (const float*)d_in[0];
    const float* x_right = (const float*)d_in[1];
    const float* cat_l   = (const float*)d_in[2];
    const float* cat_r   = (const float*)d_in[3];
    const int*   d_left  = (const int*)d_in[4];
    const int*   d_right = (const int*)d_in[5];
    const float* gamma   = (const float*)d_in[6];
    const float* beta    = (const float*)d_in[7];
    const float* rb_w1   = (const float*)d_in[8];
    const float* rb_b1   = (const float*)d_in[9];
    const float* rb_w2   = (const float*)d_in[10];
    const float* rb_b2   = (const float*)d_in[11];
    const float* bq_w    = (const float*)d_in[12];
    const float* bq_b    = (const float*)d_in[13];
    const float* bs_w    = (const float*)d_in[14];
    const float* bs_b    = (const float*)d_in[15];
    float* out = (float*)d_out;

    bn_stats_kernel<<<256, 256>>>(cat_l, gamma, beta, 0);
    bn_stats_kernel<<<256, 256>>>(cat_r, gamma, beta, 1);
    rearrange_w_kernel<<<256, 128>>>(rb_w1, 0);
    rearrange_w_kernel<<<256, 128>>>(rb_w2, 1);

    dim3 cgrid(256, 4, 2);   // 128 y-tiles x 2 x-tiles, 4 groups, 2 batch
    conv1_kernel    <<<cgrid, 256>>>(cat_l, rb_b1, 0);
    conv2proj_kernel<<<cgrid, 256>>>(cat_l, rb_b2, bq_w, bq_b, 0);   // -> g_Q
    conv1_kernel    <<<cgrid, 256>>>(cat_r, rb_b1, 1);               // g_y reused
    conv2proj_kernel<<<cgrid, 256>>>(cat_r, rb_b2, bs_w, bs_b, 1);   // -> g_K

    dim3 ggrid(4, 256, 2);
    gather_kernel<<<ggrid, 256>>>(nullptr, d_right, 0, 0, 0);  // G_Q  = gather(Q, l2r)
    gather_kernel<<<ggrid, 256>>>(nullptr, d_left,  1, 1, 1);  // G_K  = gather(K, r2l)
    gather_kernel<<<ggrid, 256>>>(x_right, d_left,  1, 2, 2);  // G_XR = gather(x_right, r2l)
    gather_kernel<<<ggrid, 256>>>(x_left,  d_right, 0, 2, 3);  // G_XL = gather(x_left, l2r)

    attn_kernel<<<dim3(1024, 2, 2), 256>>>(x_left, x_right, d_left, d_right, out);
}

// round 6
// speedup vs baseline: 2.4394x; 1.5540x over previous
#include <cuda_runtime.h>
#include <cuda_fp16.h>
#include <cstdint>

// Shapes: B=2, C=64, 4C=256, H=W=256, WS=8, hn=wn=32, P=64, DMAX=48
#define HW    65536
#define CHW4  16777216   // 256*65536
#define CHW1  4194304    // 64*65536
#define HALF_OUT 8388608 // 2*64*65536

// ------------------ device scratch (no runtime allocation) ------------------
__device__ __align__(16) __half g_yh[4L*CHW4];   // [z=side*2+b][ch256][y][x] conv1 out (fp16)
__device__ float g_Q  [2*64*65536];
__device__ float g_K  [2*64*65536];
__device__ float g_GQ [2*64*65536];    // gather_w(Q, l2r)  flat [b,y,x,c]
__device__ float g_GK [2*64*65536];    // gather_w(K, r2l)
__device__ float g_GXL[2*64*65536];    // gather_w(x_left, l2r)
__device__ float g_GXR[2*64*65536];    // gather_w(x_right, r2l)
__device__ unsigned g_w1h[4*4*4608];   // per (g,chunk): [tap9][oc64][slot8] half2
__device__ unsigned g_w2h[4*4*4608];
__device__ float g_aff[4][256];        // [0]=aL [1]=bL [2]=aR [3]=bR

__device__ __forceinline__ unsigned prmt(unsigned a, unsigned b, unsigned s) {
    unsigned r; asm("prmt.b32 %0,%1,%2,%3;" : "=r"(r) : "r"(a), "r"(b), "r"(s)); return r;
}
__device__ __forceinline__ unsigned h2bits(float lo, float hi) {
    __half2 h = __floats2half2_rn(lo, hi);
    return *(unsigned*)&h;
}

// d += A(16x16 f16) * B(16x8 f16); acc f32
#define MMA_F16(d, A0, A1, B)                                               \
    asm volatile("mma.sync.aligned.m16n8k16.row.col.f32.f16.f16.f32 "       \
        "{%0,%1,%2,%3}, {%4,%5,%6,%7}, {%8,%9}, {%0,%1,%2,%3};"             \
        : "+f"((d)[0]), "+f"((d)[1]), "+f"((d)[2]), "+f"((d)[3])            \
        : "r"((A0).x), "r"((A1).x), "r"((A0).y), "r"((A1).y),               \
          "r"((B).x), "r"((B).y))

// ------------------ BN batch stats (per channel over B,H,W) ------------------
__global__ void bn_stats_kernel(const float* __restrict__ cat,
                                const float* __restrict__ gamma,
                                const float* __restrict__ beta, int side)
{
    int ch = blockIdx.x, tid = threadIdx.x;
    const float* p0 = cat + (size_t)ch * HW;
    const float* p1 = cat + (size_t)CHW4 + (size_t)ch * HW;
    double s = 0.0, sq = 0.0;
    for (int e = tid; e < HW; e += 256) {
        float v0 = p0[e], v1 = p1[e];
        s  += (double)v0 + (double)v1;
        sq += (double)v0 * v0 + (double)v1 * v1;
    }
    __shared__ double sh_s[256], sh_q[256];
    sh_s[tid] = s; sh_q[tid] = sq;
    __syncthreads();
    for (int st = 128; st > 0; st >>= 1) {
        if (tid < st) { sh_s[tid] += sh_s[tid+st]; sh_q[tid] += sh_q[tid+st]; }
        __syncthreads();
    }
    if (tid == 0) {
        double n = 131072.0;
        double mu  = sh_s[0] / n;
        double var = sh_q[0] / n - mu * mu;
        float a = gamma[ch] * rsqrtf((float)var + 1e-5f);
        g_aff[side*2][ch]   = a;
        g_aff[side*2+1][ch] = beta[ch] - a * (float)mu;
    }
}

// ------------------ weight prep: [o][ic][3][3] -> per (g,chunk) [tap][oc][slot] half2 ------------------
// slot s holds ic pair p = (s>>1)+4*(s&1); ic = chunk*16 + 2p (lo), +1 (hi)
__global__ void prep_w_kernel(const float* __restrict__ w1, const float* __restrict__ w2)
{
    int gc = blockIdx.x;            // g*4 + chunk
    int layer = blockIdx.y;
    const float* w = layer ? w2 : w1;
    unsigned* dst = (layer ? g_w2h : g_w1h) + gc * 4608;
    int g = gc >> 2, chunk = gc & 3;
    for (int e = threadIdx.x; e < 4608; e += 256) {
        int tap = e >> 9, oc = (e >> 3) & 63, s = e & 7;
        int p = (s >> 1) + 4*(s & 1);
        int ic = chunk*16 + 2*p;
        int o = g*64 + oc;
        dst[e] = h2bits(w[(o*64 + ic)*9 + tap], w[(o*64 + ic + 1)*9 + tap]);
    }
}

// ------------------ fp16 mma conv mainloop ------------------
// Tile: 2 rows (y0,y0+1) x 128 cols. 16 warps: wset=warp>>3 picks oc half (32 oc),
// w8=warp&7: wrow=w8>>2, wx=(w8&3)*32. Per warp: 2 mfrags x 4 nfrags.
// sIn: [plane4][col130][slot8] half2 words, pitch 1064/plane. sW: [tap9][oc64][slot8].
__device__ __forceinline__ void conv_mainloop_h(
    unsigned* sIn, unsigned* sW,
    const float* __restrict__ fin, const __half* __restrict__ hin,
    const unsigned* __restrict__ wImg,
    const float* __restrict__ a_bn, const float* __restrict__ b_bn,
    int y0, int x0, int tid, float acc[2][4][4])
{
    int lane = tid & 31, warp = tid >> 5;
    int wset = warp >> 3, w8 = warp & 7, wrow = w8 >> 2, wx = (w8 & 3) * 32;
    int r4 = lane >> 2, c4 = lane & 3;

    #pragma unroll 1
    for (int chunk = 0; chunk < 4; chunk++) {
        // weights: straight float4 copy of pre-arranged image
        {
            const float4* src = (const float4*)(wImg + chunk*4608);
            float4* d4 = (float4*)sW;
            for (int e = tid; e < 1152; e += 512) d4[e] = src[e];
        }
        // interior staging: cols 1..128 (x0..x0+127), vectorized 4-wide
        for (int it = tid; it < 1024; it += 512) {
            int p = it & 7, pl = (it >> 3) & 3, j = it >> 5;
            int s = (p < 4) ? 2*p : 2*p - 7;
            int yy = y0 + pl - 1;
            int icA = chunk*16 + 2*p;
            unsigned o0, o1, o2, o3;
            if ((unsigned)yy < 256u) {
                if (fin) {
                    const float* pa = fin + (size_t)icA*HW + yy*256 + x0 + 4*j;
                    float4 a = *(const float4*)pa;
                    float4 b = *(const float4*)(pa + HW);
                    if (a_bn) {
                        float ka = a_bn[icA], ba = b_bn[icA];
                        float kb = a_bn[icA+1], bb = b_bn[icA+1];
                        a.x = fmaf(ka,a.x,ba); a.y = fmaf(ka,a.y,ba);
                        a.z = fmaf(ka,a.z,ba); a.w = fmaf(ka,a.w,ba);
                        b.x = fmaf(kb,b.x,bb); b.y = fmaf(kb,b.y,bb);
                        b.z = fmaf(kb,b.z,bb); b.w = fmaf(kb,b.w,bb);
                    }
                    o0 = h2bits(a.x, b.x); o1 = h2bits(a.y, b.y);
                    o2 = h2bits(a.z, b.z); o3 = h2bits(a.w, b.w);
                } else {
                    const unsigned* pa = (const unsigned*)(hin + (size_t)icA*HW + yy*256 + x0 + 4*j);
                    uint2 ua = *(const uint2*)pa;
                    uint2 ub = *(const uint2*)(pa + (HW/2));
                    o0 = prmt(ua.x, ub.x, 0x5410u); o1 = prmt(ua.x, ub.x, 0x7632u);
                    o2 = prmt(ua.y, ub.y, 0x5410u); o3 = prmt(ua.y, ub.y, 0x7632u);
                }
            } else { o0 = o1 = o2 = o3 = 0u; }
            int base = pl*1064 + (4*j + 1)*8 + s;
            sIn[base] = o0; sIn[base+8] = o1; sIn[base+16] = o2; sIn[base+24] = o3;
        }
        // edge cols 0 (x0-1) and 129 (x0+128)
        if (tid < 64) {
            int p = tid >> 3, pl = (tid >> 1) & 3, right = tid & 1;
            int s = (p < 4) ? 2*p : 2*p - 7;
            int yy = y0 + pl - 1;
            int xx = right ? x0 + 128 : x0 - 1;
            int col = right ? 129 : 0;
            int icA = chunk*16 + 2*p;
            unsigned o = 0u;
            if ((unsigned)yy < 256u && (unsigned)xx < 256u) {
                float lo, hi;
                size_t off = (size_t)icA*HW + yy*256 + xx;
                if (fin) {
                    lo = fin[off]; hi = fin[off + HW];
                    if (a_bn) {
                        lo = fmaf(a_bn[icA], lo, b_bn[icA]);
                        hi = fmaf(a_bn[icA+1], hi, b_bn[icA+1]);
                    }
                } else {
                    lo = __half2float(hin[off]); hi = __half2float(hin[off + HW]);
                }
                o = h2bits(lo, hi);
            }
            sIn[pl*1064 + col*8 + s] = o;
        }
        __syncthreads();

        #pragma unroll
        for (int tap = 0; tap < 9; tap++) {
            const int dy = tap / 3, dx = tap - dy*3;
            const unsigned* wB = sW + tap*512;
            uint2 A0[2], A1[2];
            #pragma unroll
            for (int mf = 0; mf < 2; mf++) {
                int oc0 = wset*32 + mf*16 + r4;
                A0[mf] = *(const uint2*)(wB + oc0*8 + 2*c4);
                A1[mf] = *(const uint2*)(wB + (oc0 + 8)*8 + 2*c4);
            }
            const unsigned* bp = sIn + (wrow + dy)*1064 + (wx + dx + r4)*8 + 2*c4;
            #pragma unroll
            for (int nf = 0; nf < 4; nf++) {
                uint2 Bf = *(const uint2*)(bp + nf*64);
                #pragma unroll
                for (int mf = 0; mf < 2; mf++)
                    MMA_F16(acc[mf][nf], A0[mf], A1[mf], Bf);
            }
        }
        __syncthreads();
    }
}

// ------------------ conv1: g_yh = fp16( leaky( conv3x3(bn(cat)) + b1 ) ) ------------------
__global__ __launch_bounds__(512, 2) void conv1_kernel(
    const float* __restrict__ cat_l, const float* __restrict__ cat_r,
    const float* __restrict__ b1)
{
    __shared__ unsigned sm[8864];   // sIn 4256 + sW 4608
    int tile = blockIdx.x, g = blockIdx.y, z = blockIdx.z;
    int side = z >> 1, b = z & 1;
    int y0 = (tile >> 1) * 2, x0 = (tile & 1) * 128;
    int tid = threadIdx.x, lane = tid & 31, warp = tid >> 5;
    int wset = warp >> 3, w8 = warp & 7, wrow = w8 >> 2, wx = (w8 & 3) * 32;
    int r4 = lane >> 2, c4 = lane & 3;

    float acc[2][4][4];
    #pragma unroll
    for (int m = 0; m < 2; m++)
        #pragma unroll
        for (int n = 0; n < 4; n++)
            #pragma unroll
            for (int k = 0; k < 4; k++) acc[m][n][k] = 0.f;

    const float* cat = side ? cat_r : cat_l;
    const float* in_base = cat + (size_t)b*CHW4 + (size_t)(g*64)*HW;
    conv_mainloop_h(sm, sm + 4256, in_base, nullptr, g_w1h + g*4*4608,
                    g_aff[side*2] + g*64, g_aff[side*2+1] + g*64,
                    y0, x0, tid, acc);

    const float* b1g = b1 + g*64;
    __half* ob = g_yh + (size_t)z*CHW4 + (size_t)(g*64)*HW + (size_t)(y0 + wrow)*256 + x0;
    #pragma unroll
    for (int mf = 0; mf < 2; mf++) {
        int oc = wset*32 + mf*16 + r4;
        float bv0 = b1g[oc], bv1 = b1g[oc + 8];
        #pragma unroll
        for (int nf = 0; nf < 4; nf++) {
            int xx = wx + nf*8 + 2*c4;
            float v0 = acc[mf][nf][0] + bv0, v1 = acc[mf][nf][1] + bv0;
            float v2 = acc[mf][nf][2] + bv1, v3 = acc[mf][nf][3] + bv1;
            v0 = (v0 > 0.f) ? v0 : 0.1f*v0;  v1 = (v1 > 0.f) ? v1 : 0.1f*v1;
            v2 = (v2 > 0.f) ? v2 : 0.1f*v2;  v3 = (v3 > 0.f) ? v3 : 0.1f*v3;
            *(__half2*)(ob + (size_t)oc*HW + xx)       = __floats2half2_rn(v0, v1);
            *(__half2*)(ob + (size_t)(oc + 8)*HW + xx) = __floats2half2_rn(v2, v3);
        }
    }
}

// ------------------ conv2 + residual + grouped 1x1 projection ------------------
__global__ __launch_bounds__(512, 2) void conv2proj_kernel(
    const float* __restrict__ cat_l, const float* __restrict__ cat_r,
    const float* __restrict__ b2,
    const float* __restrict__ bq_w, const float* __restrict__ bs_w,
    const float* __restrict__ bq_b, const float* __restrict__ bs_b)
{
    __shared__ unsigned sm[9472];   // conv: 8864; proj: resb fp32 8448 + pw 1024
    int tile = blockIdx.x, g = blockIdx.y, z = blockIdx.z;
    int side = z >> 1, b = z & 1;
    int y0 = (tile >> 1) * 2, x0 = (tile & 1) * 128;
    int tid = threadIdx.x, lane = tid & 31, warp = tid >> 5;
    int wset = warp >> 3, w8 = warp & 7, wrow = w8 >> 2, wx = (w8 & 3) * 32;
    int r4 = lane >> 2, c4 = lane & 3;

    float acc[2][4][4];
    #pragma unroll
    for (int m = 0; m < 2; m++)
        #pragma unroll
        for (int n = 0; n < 4; n++)
            #pragma unroll
            for (int k = 0; k < 4; k++) acc[m][n][k] = 0.f;

    const __half* in_base = g_yh + (size_t)z*CHW4 + (size_t)(g*64)*HW;
    conv_mainloop_h(sm, sm + 4256, nullptr, in_base, g_w2h + g*4*4608,
                    nullptr, nullptr, y0, x0, tid, acc);

    // stage 1x1 weights (fp32) — mainloop ended with syncthreads
    float* s_pw = (float*)(sm + 8448);
    {
        const float* pwsrc = (side ? bs_w : bq_w) + (size_t)(g*16)*64;
        for (int e = tid; e < 1024; e += 512) s_pw[e] = pwsrc[e];
    }

    float* resb = (float*)sm;   // [ch64][px pitch132]
    const float* cat = side ? cat_r : cat_l;
    const float* a_bn = g_aff[side*2] + g*64;
    const float* b_bn = g_aff[side*2+1] + g*64;
    const float* b2g = b2 + g*64;
    const float* pbv = (side ? bs_b : bq_b) + g*16;
    float* qout = (side ? g_K : g_Q) + (size_t)b*CHW1 + (size_t)(g*16)*HW;

    #pragma unroll 1
    for (int h2 = 0; h2 < 2; h2++) {
        __syncthreads();
        if (wrow == h2) {
            #pragma unroll
            for (int mf = 0; mf < 2; mf++) {
                int ch = wset*32 + mf*16 + r4;
                float bv0 = b2g[ch], bv1 = b2g[ch + 8];
                #pragma unroll
                for (int nf = 0; nf < 4; nf++) {
                    int px = wx + nf*8 + 2*c4;
                    *(float2*)&resb[ch*132 + px] =
                        make_float2(acc[mf][nf][0] + bv0, acc[mf][nf][1] + bv0);
                    *(float2*)&resb[(ch + 8)*132 + px] =
                        make_float2(acc[mf][nf][2] + bv1, acc[mf][nf][3] + bv1);
                }
            }
        }
        __syncthreads();
        // residual: resb += bn(cat)
        {
            const float* catb = cat + (size_t)b*CHW4 + (size_t)(g*64)*HW
                              + (size_t)(y0 + h2)*256 + x0;
            for (int e = tid; e < 8192; e += 512) {
                int ch = e >> 7, px = e & 127;
                resb[ch*132 + px] += fmaf(a_bn[ch], catb[(size_t)ch*HW + px], b_bn[ch]);
            }
        }
        __syncthreads();
        // 1x1 projection (fp32 scalar, tiny): warp = oc, lanes = px
        {
            int oc = warp;   // 0..15
            float a0 = pbv[oc], a1 = a0, a2 = a0, a3 = a0;
            const float* wr = s_pw + oc*64;
            #pragma unroll 8
            for (int ic = 0; ic < 64; ic++) {
                float wv = wr[ic];
                const float* rp = resb + ic*132 + lane;
                a0 = fmaf(wv, rp[0],  a0);
                a1 = fmaf(wv, rp[32], a1);
                a2 = fmaf(wv, rp[64], a2);
                a3 = fmaf(wv, rp[96], a3);
            }
            float* qb = qout + (size_t)oc*HW + (size_t)(y0 + h2)*256 + x0 + lane;
            qb[0] = a0; qb[32] = a1; qb[64] = a2; qb[96] = a3;
        }
    }
}

// ------------------ transpose-gather: [b,c,h,w] + idx -> flat [b,y,x,c] ------------------
__global__ __launch_bounds__(256) void gather_kernel(
    const float* __restrict__ srcParam, const int* __restrict__ dvals,
    int mode, int srcSel, int dstSel)
{
    __shared__ float s[64][113];
    int x0 = blockIdx.x * 64;
    int y  = blockIdx.y;
    int b  = blockIdx.z;
    const float* src = (srcSel == 0) ? g_Q : (srcSel == 1) ? g_K : srcParam;
    float* dst = (dstSel == 0) ? g_GQ : (dstSel == 1) ? g_GK :
                 (dstSel == 2) ? g_GXR : g_GXL;
    int lo = (mode == 0) ? x0 : max(x0 - 48, 0);
    int t = threadIdx.x;
    const float* sbp = src + (size_t)b*CHW1 + y*256;
    for (int e = t; e < 64*112; e += 256) {
        int c = e / 112, j = e - c*112;
        int col = min(lo + j, 255);
        s[c][j] = sbp[(size_t)c*HW + col];
    }
    __syncthreads();
    float* db = dst + (size_t)b*CHW1 + y*16384 + x0*64;
    const int* dp = dvals + b*HW + y*256;
    for (int e = t; e < 4096; e += 256) {
        int xi = e >> 6, c = e & 63;
        int x = x0 + xi;
        int d = dp[x];
        int sc = (mode == 0) ? min(x + d, 255) : max(x - d, 0);
        db[xi*64 + c] = s[c][sc - lo];
    }
}

// ------------------ per-window attention + output assembly ------------------
__global__ __launch_bounds__(256) void attn_kernel(
    const float* __restrict__ xl, const float* __restrict__ xr,
    const int* __restrict__ dl, const int* __restrict__ dr,
    float* __restrict__ out)
{
    __shared__ __align__(16) float sA[64][68];
    __shared__ __align__(16) float sB[64][68];
    __shared__ float mu[8];
    int win = blockIdx.x, side = blockIdx.y, b = blockIdx.z;
    int hi = win >> 5, wi = win & 31;
    int t = threadIdx.x;

    const float *Ab, *Bb, *Xb;
    if (side == 0) { Ab = g_Q; Bb = g_GK; Xb = g_GXR; }
    else           { Ab = g_K; Bb = g_GQ; Xb = g_GXL; }
    size_t base = (size_t)b*CHW1 + (size_t)(hi*8)*256 + wi*8;

    for (int e = t; e < 4096; e += 256) {
        int j = e & 63, c = e >> 6;
        size_t off = base + (size_t)c*HW + (j >> 3)*256 + (j & 7);
        sA[j][c] = Ab[off];
        sB[j][c] = Bb[off];
    }
    __syncthreads();

    {
        int w = t >> 5, lane = t & 31;
        float s = 0.f;
        int row = w*8 + (lane >> 2);
        int c0  = (lane & 3) * 16;
        #pragma unroll
        for (int m = 0; m < 16; m++) s += sB[row][c0 + m];
        #pragma unroll
        for (int o = 16; o; o >>= 1) s += __shfl_xor_sync(0xffffffffu, s, o);
        if (lane == 0) mu[w] = s * (1.f/512.f);
    }
    __syncthreads();
    {
        int j = t >> 2, cb = t & 3;
        float m = mu[j >> 3];
        #pragma unroll
        for (int k = 0; k < 16; k++) sB[j][cb + 4*k] -= m;
    }
    __syncthreads();

    int i = t >> 2, jq = t & 3;
    float S[16];
    #pragma unroll
    for (int k = 0; k < 16; k++) S[k] = 0.f;
    #pragma unroll 4
    for (int c4 = 0; c4 < 16; c4++) {
        float4 a4 = *(const float4*)&sA[i][c4*4];
        #pragma unroll
        for (int k = 0; k < 16; k++) {
            float4 b4 = *(const float4*)&sB[jq + 4*k][c4*4];
            S[k] = fmaf(a4.x, b4.x, S[k]);
            S[k] = fmaf(a4.y, b4.y, S[k]);
            S[k] = fmaf(a4.z, b4.z, S[k]);
            S[k] = fmaf(a4.w, b4.w, S[k]);
        }
    }
    float mx = S[0];
    #pragma unroll
    for (int k = 1; k < 16; k++) mx = fmaxf(mx, S[k]);
    mx = fmaxf(mx, __shfl_xor_sync(0xffffffffu, mx, 1));
    mx = fmaxf(mx, __shfl_xor_sync(0xffffffffu, mx, 2));
    float sum = 0.f;
    #pragma unroll
    for (int k = 0; k < 16; k++) { S[k] = __expf(S[k] - mx); sum += S[k]; }
    sum += __shfl_xor_sync(0xffffffffu, sum, 1);
    sum += __shfl_xor_sync(0xffffffffu, sum, 2);
    float inv = 1.f / sum;

    __syncthreads();
    #pragma unroll
    for (int k = 0; k < 16; k++) sA[i][jq + 4*k] = S[k] * inv;
    for (int e = t; e < 4096; e += 256) {
        int j = e & 63, c = e >> 6;
        sB[j][c] = Xb[base + (size_t)c*HW + (j >> 3)*256 + (j & 7)];
    }
    __syncthreads();

    float4 acc[4];
    #pragma unroll
    for (int k = 0; k < 4; k++) acc[k] = make_float4(0.f, 0.f, 0.f, 0.f);
    #pragma unroll 4
    for (int j = 0; j < 64; j++) {
        float m = sA[i][j];
        #pragma unroll
        for (int k = 0; k < 4; k++) {
            float4 x4 = *(const float4*)&sB[j][(jq + 4*k)*4];
            acc[k].x = fmaf(m, x4.x, acc[k].x);
            acc[k].y = fmaf(m, x4.y, acc[k].y);
            acc[k].z = fmaf(m, x4.z, acc[k].z);
            acc[k].w = fmaf(m, x4.w, acc[k].w);
        }
    }

    int p = i >> 3, q = i & 7;
    int Y = hi*8 + p, Xw = wi*8 + q;
    const float* xbase;
    float mval;
    if (side == 0) {
        xbase = xl;
        int d = dl[b*HW + Y*256 + Xw];
        mval = (Xw - d >= 0) ? 1.f : 0.f;
    } else {
        xbase = xr;
        int d = dr[b*HW + Y*256 + Xw];
        mval = (Xw + d <= 255) ? 1.f : 0.f;
    }
    float* op = out + (size_t)side*HALF_OUT + (size_t)b*CHW1 + Y*256 + Xw;
    const float* xp = xbase + (size_t)b*CHW1 + Y*256 + Xw;
    #pragma unroll
    for (int k = 0; k < 4; k++) {
        int cb = (jq + 4*k) * 4;
        float vals[4] = {acc[k].x, acc[k].y, acc[k].z, acc[k].w};
        #pragma unroll
        for (int e = 0; e < 4; e++) {
            size_t go = (size_t)(cb + e) * HW;
            op[go] = xp[go] + vals[e] * mval;
        }
    }
}

// ------------------ launch ------------------
extern "C" void kernel_launch(void* const* d_in, const int* in_sizes, int n_in,
                              void* d_out, int out_size)
{
    (void)in_sizes; (void)n_in; (void)out_size;
    const float* x_left  = (const float*)d_in[0];
    const float* x_right = (const float*)d_in[1];
    const float* cat_l   = (const float*)d_in[2];
    const float* cat_r   = (const float*)d_in[3];
    const int*   d_left  = (const int*)d_in[4];
    const int*   d_right = (const int*)d_in[5];
    const float* gamma   = (const float*)d_in[6];
    const float* beta    = (const float*)d_in[7];
    const float* rb_w1   = (const float*)d_in[8];
    const float* rb_b1   = (const float*)d_in[9];
    const float* rb_w2   = (const float*)d_in[10];
    const float* rb_b2   = (const float*)d_in[11];
    const float* bq_w    = (const float*)d_in[12];
    const float* bq_b    = (const float*)d_in[13];
    const float* bs_w    = (const float*)d_in[14];
    const float* bs_b    = (const float*)d_in[15];
    float* out = (float*)d_out;

    bn_stats_kernel<<<256, 256>>>(cat_l, gamma, beta, 0);
    bn_stats_kernel<<<256, 256>>>(cat_r, gamma, beta, 1);
    prep_w_kernel<<<dim3(16, 2), 256>>>(rb_w1, rb_w2);

    dim3 cgrid(256, 4, 4);   // 128 y-tiles x 2 x-halves, 4 groups, z = side*2+b
    conv1_kernel   <<<cgrid, 512>>>(cat_l, cat_r, rb_b1);
    conv2proj_kernel<<<cgrid, 512>>>(cat_l, cat_r, rb_b2, bq_w, bs_w, bq_b, bs_b);

    dim3 ggrid(4, 256, 2);
    gather_kernel<<<ggrid, 256>>>(nullptr, d_right, 0, 0, 0);  // G_Q  = gather(Q, l2r)
    gather_kernel<<<ggrid, 256>>>(nullptr, d_left,  1, 1, 1);  // G_K  = gather(K, r2l)
    gather_kernel<<<ggrid, 256>>>(x_right, d_left,  1, 2, 2);  // G_XR = gather(x_right, r2l)
    gather_kernel<<<ggrid, 256>>>(x_left,  d_right, 0, 2, 3);  // G_XL = gather(x_left, l2r)

    attn_kernel<<<dim3(1024, 2, 2), 256>>>(x_left, x_right, d_left, d_right, out);
}

// round 7
// speedup vs baseline: 3.0292x; 1.2418x over previous
#include <cuda_runtime.h>
#include <cuda_fp16.h>
#include <cstdint>

// Shapes: B=2, C=64, 4C=256, H=W=256, WS=8, hn=wn=32, P=64, DMAX=48
#define HW    65536
#define CHW4  16777216   // 256*65536
#define CHW1  4194304    // 64*65536
#define HALF_OUT 8388608 // 2*64*65536

// ------------------ device scratch (no runtime allocation) ------------------
__device__ __align__(16) __half g_yh[4L*CHW4];   // [z=side*2+b][ch256][y][x] conv1 out (fp16)
__device__ float g_Q  [2*64*65536];
__device__ float g_K  [2*64*65536];
__device__ float g_GQ [2*64*65536];    // gather_w(Q, l2r)  flat [b,y,x,c]
__device__ float g_GK [2*64*65536];    // gather_w(K, r2l)
__device__ float g_GXL[2*64*65536];    // gather_w(x_left, l2r)
__device__ float g_GXR[2*64*65536];    // gather_w(x_right, r2l)
__device__ unsigned g_w1h[4*4*4608];   // per (g,chunk): [tap9][oc64][slot8] half2
__device__ unsigned g_w2h[4*4*4608];
__device__ float g_aff[4][256];        // [0]=aL [1]=bL [2]=aR [3]=bR

__device__ __forceinline__ unsigned prmt(unsigned a, unsigned b, unsigned s) {
    unsigned r; asm("prmt.b32 %0,%1,%2,%3;" : "=r"(r) : "r"(a), "r"(b), "r"(s)); return r;
}
__device__ __forceinline__ unsigned h2bits(float lo, float hi) {
    __half2 h = __floats2half2_rn(lo, hi);
    return *(unsigned*)&h;
}

// d += A(16x16 f16) * B(16x8 f16); acc f32.  A regs: (r,klo),(r+8,klo),(r,khi),(r+8,khi)
#define MMA_F16(d, A0, A1, B)                                               \
    asm volatile("mma.sync.aligned.m16n8k16.row.col.f32.f16.f16.f32 "       \
        "{%0,%1,%2,%3}, {%4,%5,%6,%7}, {%8,%9}, {%0,%1,%2,%3};"             \
        : "+f"((d)[0]), "+f"((d)[1]), "+f"((d)[2]), "+f"((d)[3])            \
        : "r"((A0).x), "r"((A1).x), "r"((A0).y), "r"((A1).y),               \
          "r"((B).x), "r"((B).y))
#define MMA_F16S(d, a0, a1, a2, a3, b0, b1)                                 \
    asm volatile("mma.sync.aligned.m16n8k16.row.col.f32.f16.f16.f32 "       \
        "{%0,%1,%2,%3}, {%4,%5,%6,%7}, {%8,%9}, {%0,%1,%2,%3};"             \
        : "+f"((d)[0]), "+f"((d)[1]), "+f"((d)[2]), "+f"((d)[3])            \
        : "r"(a0), "r"(a1), "r"(a2), "r"(a3), "r"(b0), "r"(b1))

// ------------------ BN batch stats (per channel over B,H,W) ------------------
__global__ void bn_stats_kernel(const float* __restrict__ cat,
                                const float* __restrict__ gamma,
                                const float* __restrict__ beta, int side)
{
    int ch = blockIdx.x, tid = threadIdx.x;
    const float* p0 = cat + (size_t)ch * HW;
    const float* p1 = cat + (size_t)CHW4 + (size_t)ch * HW;
    double s = 0.0, sq = 0.0;
    for (int e = tid; e < HW; e += 256) {
        float v0 = p0[e], v1 = p1[e];
        s  += (double)v0 + (double)v1;
        sq += (double)v0 * v0 + (double)v1 * v1;
    }
    __shared__ double sh_s[256], sh_q[256];
    sh_s[tid] = s; sh_q[tid] = sq;
    __syncthreads();
    for (int st = 128; st > 0; st >>= 1) {
        if (tid < st) { sh_s[tid] += sh_s[tid+st]; sh_q[tid] += sh_q[tid+st]; }
        __syncthreads();
    }
    if (tid == 0) {
        double n = 131072.0;
        double mu  = sh_s[0] / n;
        double var = sh_q[0] / n - mu * mu;
        float a = gamma[ch] * rsqrtf((float)var + 1e-5f);
        g_aff[side*2][ch]   = a;
        g_aff[side*2+1][ch] = beta[ch] - a * (float)mu;
    }
}

// ------------------ weight prep: [o][ic][3][3] -> per (g,chunk) [tap][oc][slot] half2 ------------------
__global__ void prep_w_kernel(const float* __restrict__ w1, const float* __restrict__ w2)
{
    int gc = blockIdx.x;            // g*4 + chunk
    int layer = blockIdx.y;
    const float* w = layer ? w2 : w1;
    unsigned* dst = (layer ? g_w2h : g_w1h) + gc * 4608;
    int g = gc >> 2, chunk = gc & 3;
    for (int e = threadIdx.x; e < 4608; e += 256) {
        int tap = e >> 9, oc = (e >> 3) & 63, s = e & 7;
        int p = (s >> 1) + 4*(s & 1);
        int ic = chunk*16 + 2*p;
        int o = g*64 + oc;
        dst[e] = h2bits(w[(o*64 + ic)*9 + tap], w[(o*64 + ic + 1)*9 + tap]);
    }
}

// ------------------ fp16 mma conv mainloop (unchanged from R6) ------------------
__device__ __forceinline__ void conv_mainloop_h(
    unsigned* sIn, unsigned* sW,
    const float* __restrict__ fin, const __half* __restrict__ hin,
    const unsigned* __restrict__ wImg,
    const float* __restrict__ a_bn, const float* __restrict__ b_bn,
    int y0, int x0, int tid, float acc[2][4][4])
{
    int lane = tid & 31, warp = tid >> 5;
    int wset = warp >> 3, w8 = warp & 7, wrow = w8 >> 2, wx = (w8 & 3) * 32;
    int r4 = lane >> 2, c4 = lane & 3;

    #pragma unroll 1
    for (int chunk = 0; chunk < 4; chunk++) {
        {
            const float4* src = (const float4*)(wImg + chunk*4608);
            float4* d4 = (float4*)sW;
            for (int e = tid; e < 1152; e += 512) d4[e] = src[e];
        }
        for (int it = tid; it < 1024; it += 512) {
            int p = it & 7, pl = (it >> 3) & 3, j = it >> 5;
            int s = (p < 4) ? 2*p : 2*p - 7;
            int yy = y0 + pl - 1;
            int icA = chunk*16 + 2*p;
            unsigned o0, o1, o2, o3;
            if ((unsigned)yy < 256u) {
                if (fin) {
                    const float* pa = fin + (size_t)icA*HW + yy*256 + x0 + 4*j;
                    float4 a = *(const float4*)pa;
                    float4 b = *(const float4*)(pa + HW);
                    if (a_bn) {
                        float ka = a_bn[icA], ba = b_bn[icA];
                        float kb = a_bn[icA+1], bb = b_bn[icA+1];
                        a.x = fmaf(ka,a.x,ba); a.y = fmaf(ka,a.y,ba);
                        a.z = fmaf(ka,a.z,ba); a.w = fmaf(ka,a.w,ba);
                        b.x = fmaf(kb,b.x,bb); b.y = fmaf(kb,b.y,bb);
                        b.z = fmaf(kb,b.z,bb); b.w = fmaf(kb,b.w,bb);
                    }
                    o0 = h2bits(a.x, b.x); o1 = h2bits(a.y, b.y);
                    o2 = h2bits(a.z, b.z); o3 = h2bits(a.w, b.w);
                } else {
                    const unsigned* pa = (const unsigned*)(hin + (size_t)icA*HW + yy*256 + x0 + 4*j);
                    uint2 ua = *(const uint2*)pa;
                    uint2 ub = *(const uint2*)(pa + (HW/2));
                    o0 = prmt(ua.x, ub.x, 0x5410u); o1 = prmt(ua.x, ub.x, 0x7632u);
                    o2 = prmt(ua.y, ub.y, 0x5410u); o3 = prmt(ua.y, ub.y, 0x7632u);
                }
            } else { o0 = o1 = o2 = o3 = 0u; }
            int base = pl*1064 + (4*j + 1)*8 + s;
            sIn[base] = o0; sIn[base+8] = o1; sIn[base+16] = o2; sIn[base+24] = o3;
        }
        if (tid < 64) {
            int p = tid >> 3, pl = (tid >> 1) & 3, right = tid & 1;
            int s = (p < 4) ? 2*p : 2*p - 7;
            int yy = y0 + pl - 1;
            int xx = right ? x0 + 128 : x0 - 1;
            int col = right ? 129 : 0;
            int icA = chunk*16 + 2*p;
            unsigned o = 0u;
            if ((unsigned)yy < 256u && (unsigned)xx < 256u) {
                float lo, hi;
                size_t off = (size_t)icA*HW + yy*256 + xx;
                if (fin) {
                    lo = fin[off]; hi = fin[off + HW];
                    if (a_bn) {
                        lo = fmaf(a_bn[icA], lo, b_bn[icA]);
                        hi = fmaf(a_bn[icA+1], hi, b_bn[icA+1]);
                    }
                } else {
                    lo = __half2float(hin[off]); hi = __half2float(hin[off + HW]);
                }
                o = h2bits(lo, hi);
            }
            sIn[pl*1064 + col*8 + s] = o;
        }
        __syncthreads();

        #pragma unroll
        for (int tap = 0; tap < 9; tap++) {
            const int dy = tap / 3, dx = tap - dy*3;
            const unsigned* wB = sW + tap*512;
            uint2 A0[2], A1[2];
            #pragma unroll
            for (int mf = 0; mf < 2; mf++) {
                int oc0 = wset*32 + mf*16 + r4;
                A0[mf] = *(const uint2*)(wB + oc0*8 + 2*c4);
                A1[mf] = *(const uint2*)(wB + (oc0 + 8)*8 + 2*c4);
            }
            const unsigned* bp = sIn + (wrow + dy)*1064 + (wx + dx + r4)*8 + 2*c4;
            #pragma unroll
            for (int nf = 0; nf < 4; nf++) {
                uint2 Bf = *(const uint2*)(bp + nf*64);
                #pragma unroll
                for (int mf = 0; mf < 2; mf++)
                    MMA_F16(acc[mf][nf], A0[mf], A1[mf], Bf);
            }
        }
        __syncthreads();
    }
}

// ------------------ conv1: g_yh = fp16( leaky( conv3x3(bn(cat)) + b1 ) ) ------------------
__global__ __launch_bounds__(512, 2) void conv1_kernel(
    const float* __restrict__ cat_l, const float* __restrict__ cat_r,
    const float* __restrict__ b1)
{
    __shared__ unsigned sm[8864];
    int tile = blockIdx.x, g = blockIdx.y, z = blockIdx.z;
    int side = z >> 1, b = z & 1;
    int y0 = (tile >> 1) * 2, x0 = (tile & 1) * 128;
    int tid = threadIdx.x, lane = tid & 31, warp = tid >> 5;
    int wset = warp >> 3, w8 = warp & 7, wrow = w8 >> 2, wx = (w8 & 3) * 32;
    int r4 = lane >> 2, c4 = lane & 3;

    float acc[2][4][4];
    #pragma unroll
    for (int m = 0; m < 2; m++)
        #pragma unroll
        for (int n = 0; n < 4; n++)
            #pragma unroll
            for (int k = 0; k < 4; k++) acc[m][n][k] = 0.f;

    const float* cat = side ? cat_r : cat_l;
    const float* in_base = cat + (size_t)b*CHW4 + (size_t)(g*64)*HW;
    conv_mainloop_h(sm, sm + 4256, in_base, nullptr, g_w1h + g*4*4608,
                    g_aff[side*2] + g*64, g_aff[side*2+1] + g*64,
                    y0, x0, tid, acc);

    const float* b1g = b1 + g*64;
    __half* ob = g_yh + (size_t)z*CHW4 + (size_t)(g*64)*HW + (size_t)(y0 + wrow)*256 + x0;
    #pragma unroll
    for (int mf = 0; mf < 2; mf++) {
        int oc = wset*32 + mf*16 + r4;
        float bv0 = b1g[oc], bv1 = b1g[oc + 8];
        #pragma unroll
        for (int nf = 0; nf < 4; nf++) {
            int xx = wx + nf*8 + 2*c4;
            float v0 = acc[mf][nf][0] + bv0, v1 = acc[mf][nf][1] + bv0;
            float v2 = acc[mf][nf][2] + bv1, v3 = acc[mf][nf][3] + bv1;
            v0 = (v0 > 0.f) ? v0 : 0.1f*v0;  v1 = (v1 > 0.f) ? v1 : 0.1f*v1;
            v2 = (v2 > 0.f) ? v2 : 0.1f*v2;  v3 = (v3 > 0.f) ? v3 : 0.1f*v3;
            *(__half2*)(ob + (size_t)oc*HW + xx)       = __floats2half2_rn(v0, v1);
            *(__half2*)(ob + (size_t)(oc + 8)*HW + xx) = __floats2half2_rn(v2, v3);
        }
    }
}

// ------------------ conv2 + residual + grouped 1x1 projection (mma epilogue) ------------------
__global__ __launch_bounds__(512, 2) void conv2proj_kernel(
    const float* __restrict__ cat_l, const float* __restrict__ cat_r,
    const float* __restrict__ b2,
    const float* __restrict__ bq_w, const float* __restrict__ bs_w,
    const float* __restrict__ bq_b, const float* __restrict__ bs_b)
{
    __shared__ unsigned sm[9728];   // conv: [0,8864); epi: resbh halves [0,9216) + pwh [9216,9728)
    int tile = blockIdx.x, g = blockIdx.y, z = blockIdx.z;
    int side = z >> 1, b = z & 1;
    int y0 = (tile >> 1) * 2, x0 = (tile & 1) * 128;
    int tid = threadIdx.x, lane = tid & 31, warp = tid >> 5;
    int wset = warp >> 3, w8 = warp & 7, wrow = w8 >> 2, wx = (w8 & 3) * 32;
    int r4 = lane >> 2, c4 = lane & 3;

    float acc[2][4][4];
    #pragma unroll
    for (int m = 0; m < 2; m++)
        #pragma unroll
        for (int n = 0; n < 4; n++)
            #pragma unroll
            for (int k = 0; k < 4; k++) acc[m][n][k] = 0.f;

    const __half* in_base = g_yh + (size_t)z*CHW4 + (size_t)(g*64)*HW;
    conv_mainloop_h(sm, sm + 4256, nullptr, in_base, g_w2h + g*4*4608,
                    nullptr, nullptr, y0, x0, tid, acc);
    // mainloop ends with __syncthreads: all smem reads done

    __half* resbh = (__half*)sm;              // [256 px][72 halves]
    unsigned* pwh = sm + 9216;                // [16 oc][32 slot words]
    const float* cat = side ? cat_r : cat_l;
    const float* a_bn = g_aff[side*2] + g*64;
    const float* b_bn = g_aff[side*2+1] + g*64;
    const float* b2g = b2 + g*64;
    const float* pbg = (side ? bs_b : bq_b) + g*16;
    float* qout = (side ? g_K : g_Q) + (size_t)b*CHW1 + (size_t)(g*16)*HW;

    // stage 1x1 weights fp16 slot layout
    {
        const float* pwsrc = (side ? bs_w : bq_w) + (size_t)(g*16)*64;
        int e = tid;
        if (e < 512) {
            int oc = e >> 5, w5 = e & 31;
            int kc = w5 >> 3, s = w5 & 7;
            int p = (s >> 1) + 4*(s & 1);
            int ic0 = kc*16 + 2*p;
            pwh[e] = h2bits(pwsrc[oc*64 + ic0], pwsrc[oc*64 + ic0 + 1]);
        }
    }
    // resb = conv2 + b2 + bn(cat), fp16, layout [px_lin = wrow*128+px][ch]
    {
        const float* catb = cat + (size_t)b*CHW4 + (size_t)(g*64)*HW
                          + (size_t)(y0 + wrow)*256 + x0;
        #pragma unroll
        for (int mf = 0; mf < 2; mf++) {
            int ch = wset*32 + mf*16 + r4;
            float bv0 = b2g[ch], bv1 = b2g[ch + 8];
            float a0c = a_bn[ch], b0c = b_bn[ch];
            float a1c = a_bn[ch+8], b1c = b_bn[ch+8];
            #pragma unroll
            for (int nf = 0; nf < 4; nf++) {
                int px = wx + nf*8 + 2*c4;
                int pxl = wrow*128 + px;
                float2 cv0 = *(const float2*)&catb[(size_t)ch*HW + px];
                float2 cv1 = *(const float2*)&catb[(size_t)(ch+8)*HW + px];
                resbh[pxl*72 + ch]       = __float2half_rn(acc[mf][nf][0] + bv0 + fmaf(a0c, cv0.x, b0c));
                resbh[(pxl+1)*72 + ch]   = __float2half_rn(acc[mf][nf][1] + bv0 + fmaf(a0c, cv0.y, b0c));
                resbh[pxl*72 + ch+8]     = __float2half_rn(acc[mf][nf][2] + bv1 + fmaf(a1c, cv1.x, b1c));
                resbh[(pxl+1)*72 + ch+8] = __float2half_rn(acc[mf][nf][3] + bv1 + fmaf(a1c, cv1.y, b1c));
            }
        }
    }
    __syncthreads();
    // proj mma: warp w covers px rows w*16..w*16+15; N=16 oc, K=64
    {
        int pm0 = warp * 16;
        float PA[2][4];
        #pragma unroll
        for (int nf = 0; nf < 2; nf++) {
            float p0 = pbg[8*nf + 2*c4], p1 = pbg[8*nf + 2*c4 + 1];
            PA[nf][0] = p0; PA[nf][1] = p1; PA[nf][2] = p0; PA[nf][3] = p1;
        }
        #pragma unroll
        for (int kc = 0; kc < 4; kc++) {
            unsigned a0 = *(const unsigned*)&resbh[(pm0 + r4)*72 + kc*16 + 2*c4];
            unsigned a2 = *(const unsigned*)&resbh[(pm0 + r4)*72 + kc*16 + 2*c4 + 8];
            unsigned a1 = *(const unsigned*)&resbh[(pm0 + r4 + 8)*72 + kc*16 + 2*c4];
            unsigned a3 = *(const unsigned*)&resbh[(pm0 + r4 + 8)*72 + kc*16 + 2*c4 + 8];
            #pragma unroll
            for (int nf = 0; nf < 2; nf++) {
                uint2 bb = *(const uint2*)&pwh[(nf*8 + r4)*32 + kc*8 + 2*c4];
                MMA_F16S(PA[nf], a0, a1, a2, a3, bb.x, bb.y);
            }
        }
        #pragma unroll
        for (int nf = 0; nf < 2; nf++)
            #pragma unroll
            for (int e = 0; e < 2; e++) {
                int oc = 8*nf + 2*c4 + e;
                int pxa = pm0 + r4, pxb = pxa + 8;
                qout[(size_t)oc*HW + (size_t)(y0 + (pxa >> 7))*256 + x0 + (pxa & 127)] = PA[nf][e];
                qout[(size_t)oc*HW + (size_t)(y0 + (pxb >> 7))*256 + x0 + (pxb & 127)] = PA[nf][2+e];
            }
    }
}

// ------------------ transpose-gather: [b,c,h,w] + idx -> flat [b,y,x,c] ------------------
__global__ __launch_bounds__(256) void gather_kernel(
    const float* __restrict__ srcParam, const int* __restrict__ dvals,
    int mode, int srcSel, int dstSel)
{
    __shared__ float s[64][113];
    int x0 = blockIdx.x * 64;
    int y  = blockIdx.y;
    int b  = blockIdx.z;
    const float* src = (srcSel == 0) ? g_Q : (srcSel == 1) ? g_K : srcParam;
    float* dst = (dstSel == 0) ? g_GQ : (dstSel == 1) ? g_GK :
                 (dstSel == 2) ? g_GXR : g_GXL;
    int lo = (mode == 0) ? x0 : max(x0 - 48, 0);
    int t = threadIdx.x;
    const float* sbp = src + (size_t)b*CHW1 + y*256;
    for (int e = t; e < 64*112; e += 256) {
        int c = e / 112, j = e - c*112;
        int col = min(lo + j, 255);
        s[c][j] = sbp[(size_t)c*HW + col];
    }
    __syncthreads();
    float* db = dst + (size_t)b*CHW1 + y*16384 + x0*64;
    const int* dp = dvals + b*HW + y*256;
    for (int e = t; e < 4096; e += 256) {
        int xi = e >> 6, c = e & 63;
        int x = x0 + xi;
        int d = dp[x];
        int sc = (mode == 0) ? min(x + d, 255) : max(x - d, 0);
        db[xi*64 + c] = s[c][sc - lo];
    }
}

// ------------------ per-window attention (fp16 mma) + output assembly ------------------
__global__ __launch_bounds__(128) void attn_kernel(
    const float* __restrict__ xl, const float* __restrict__ xr,
    const int* __restrict__ dl, const int* __restrict__ dr,
    float* __restrict__ out)
{
    __shared__ float sRaw[64][68];
    __shared__ __align__(16) unsigned sA[2048];   // [row][kc*8+slot] half2
    __shared__ __align__(16) unsigned sB[2048];
    __shared__ float mu[8];
    int win = blockIdx.x, side = blockIdx.y, b = blockIdx.z;
    int hi = win >> 5, wi = win & 31;
    int t = threadIdx.x, lane = t & 31, warp = t >> 5;
    int q4 = lane & 3, r4 = lane >> 2;

    const float *Ab, *Bb, *Xb;
    if (side == 0) { Ab = g_Q; Bb = g_GK; Xb = g_GXR; }
    else           { Ab = g_K; Bb = g_GQ; Xb = g_GXL; }
    size_t base = (size_t)b*CHW1 + (size_t)(hi*8)*256 + wi*8;

    // ---- stage A (Q patch) and pack fp16 [i][c-slots]
    for (int e = t; e < 4096; e += 128) {
        int j = e & 63, c = e >> 6;
        sRaw[j][c] = Ab[base + (size_t)c*HW + ((j >> 3)*256 + (j & 7))];
    }
    __syncthreads();
    for (int e = t; e < 2048; e += 128) {
        int i = e >> 5, w5 = e & 31;
        int kc = w5 >> 3, s = w5 & 7;
        int p = (s >> 1) + 4*(s & 1);
        int c0 = kc*16 + 2*p;
        sA[e] = h2bits(sRaw[i][c0], sRaw[i][c0+1]);
    }
    __syncthreads();
    // ---- stage K_sel raw, mean-center per p-block, pack fp16 [j][c-slots]
    for (int e = t; e < 4096; e += 128) {
        int j = e & 63, c = e >> 6;
        sRaw[j][c] = Bb[base + (size_t)c*HW + ((j >> 3)*256 + (j & 7))];
    }
    __syncthreads();
    {
        int p = t >> 4, sub = t & 15;
        float s = 0.f;
        #pragma unroll 4
        for (int m = 0; m < 32; m++) {
            int el = sub*32 + m;
            s += sRaw[8*p + (el >> 6)][el & 63];
        }
        s += __shfl_xor_sync(~0u, s, 8);
        s += __shfl_xor_sync(~0u, s, 4);
        s += __shfl_xor_sync(~0u, s, 2);
        s += __shfl_xor_sync(~0u, s, 1);
        if (sub == 0) mu[p] = s * (1.f/512.f);
    }
    __syncthreads();
    for (int e = t; e < 2048; e += 128) {
        int j = e >> 5, w5 = e & 31;
        int kc = w5 >> 3, s = w5 & 7;
        int p = (s >> 1) + 4*(s & 1);
        int c0 = kc*16 + 2*p;
        float m = mu[j >> 3];
        sB[e] = h2bits(sRaw[j][c0] - m, sRaw[j][c0+1] - m);
    }
    __syncthreads();

    // ---- scores: warp does rows m0..m0+15, all 64 j
    int m0 = warp * 16;
    float S[8][4];
    #pragma unroll
    for (int nf = 0; nf < 8; nf++)
        #pragma unroll
        for (int k = 0; k < 4; k++) S[nf][k] = 0.f;
    #pragma unroll
    for (int kc = 0; kc < 4; kc++) {
        uint2 alo = *(const uint2*)&sA[(m0 + r4)*32 + kc*8 + q4*2];
        uint2 ahi = *(const uint2*)&sA[(m0 + r4 + 8)*32 + kc*8 + q4*2];
        #pragma unroll
        for (int nf = 0; nf < 8; nf++) {
            uint2 bb = *(const uint2*)&sB[(nf*8 + r4)*32 + kc*8 + q4*2];
            MMA_F16S(S[nf], alo.x, ahi.x, alo.y, ahi.y, bb.x, bb.y);
        }
    }
    // ---- softmax over j for rows ilo = m0+r4, ihi = +8
    float mlo = -1e30f, mhi = -1e30f;
    #pragma unroll
    for (int nf = 0; nf < 8; nf++) {
        mlo = fmaxf(mlo, fmaxf(S[nf][0], S[nf][1]));
        mhi = fmaxf(mhi, fmaxf(S[nf][2], S[nf][3]));
    }
    mlo = fmaxf(mlo, __shfl_xor_sync(~0u, mlo, 1));
    mlo = fmaxf(mlo, __shfl_xor_sync(~0u, mlo, 2));
    mhi = fmaxf(mhi, __shfl_xor_sync(~0u, mhi, 1));
    mhi = fmaxf(mhi, __shfl_xor_sync(~0u, mhi, 2));
    float slo = 0.f, shi = 0.f;
    #pragma unroll
    for (int nf = 0; nf < 8; nf++) {
        S[nf][0] = __expf(S[nf][0] - mlo); S[nf][1] = __expf(S[nf][1] - mlo);
        S[nf][2] = __expf(S[nf][2] - mhi); S[nf][3] = __expf(S[nf][3] - mhi);
        slo += S[nf][0] + S[nf][1];
        shi += S[nf][2] + S[nf][3];
    }
    slo += __shfl_xor_sync(~0u, slo, 1);
    slo += __shfl_xor_sync(~0u, slo, 2);
    shi += __shfl_xor_sync(~0u, shi, 1);
    shi += __shfl_xor_sync(~0u, shi, 2);
    float invlo = 1.f / slo, invhi = 1.f / shi;
    // probs -> A fragments (register repack; C layout == A layout)
    unsigned pa[4][4];
    #pragma unroll
    for (int kc = 0; kc < 4; kc++) {
        pa[kc][0] = h2bits(S[2*kc][0]*invlo,   S[2*kc][1]*invlo);
        pa[kc][1] = h2bits(S[2*kc][2]*invhi,   S[2*kc][3]*invhi);
        pa[kc][2] = h2bits(S[2*kc+1][0]*invlo, S[2*kc+1][1]*invlo);
        pa[kc][3] = h2bits(S[2*kc+1][2]*invhi, S[2*kc+1][3]*invhi);
    }
    __syncthreads();    // all warps done reading sB/sRaw

    // ---- stage X raw, pack fp16 transposed [c][j-slots]
    for (int e = t; e < 4096; e += 128) {
        int j = e & 63, c = e >> 6;
        sRaw[j][c] = Xb[base + (size_t)c*HW + ((j >> 3)*256 + (j & 7))];
    }
    __syncthreads();
    for (int e = t; e < 2048; e += 128) {
        int c = e >> 5, w5 = e & 31;
        int kc = w5 >> 3, s = w5 & 7;
        int p = (s >> 1) + 4*(s & 1);
        int j0 = kc*16 + 2*p;
        sB[e] = h2bits(sRaw[j0][c], sRaw[j0+1][c]);
    }
    __syncthreads();
    // ---- apply: O[i][c] = M @ X
    float O[8][4];
    #pragma unroll
    for (int nf = 0; nf < 8; nf++)
        #pragma unroll
        for (int k = 0; k < 4; k++) O[nf][k] = 0.f;
    #pragma unroll
    for (int kc = 0; kc < 4; kc++) {
        #pragma unroll
        for (int nf = 0; nf < 8; nf++) {
            uint2 bb = *(const uint2*)&sB[(nf*8 + r4)*32 + kc*8 + q4*2];
            MMA_F16S(O[nf], pa[kc][0], pa[kc][1], pa[kc][2], pa[kc][3], bb.x, bb.y);
        }
    }
    // ---- output: out = x + O * mask
    int ilo = m0 + r4, ihi = ilo + 8;
    int Ylo = hi*8 + (ilo >> 3), Xlo = wi*8 + (ilo & 7);
    int Yhi = hi*8 + (ihi >> 3), Xhi = wi*8 + (ihi & 7);
    const float* xbase = side ? xr : xl;
    float mv_lo, mv_hi;
    if (side == 0) {
        mv_lo = (Xlo - dl[b*HW + Ylo*256 + Xlo] >= 0) ? 1.f : 0.f;
        mv_hi = (Xhi - dl[b*HW + Yhi*256 + Xhi] >= 0) ? 1.f : 0.f;
    } else {
        mv_lo = (Xlo + dr[b*HW + Ylo*256 + Xlo] <= 255) ? 1.f : 0.f;
        mv_hi = (Xhi + dr[b*HW + Yhi*256 + Xhi] <= 255) ? 1.f : 0.f;
    }
    size_t offlo = (size_t)b*CHW1 + Ylo*256 + Xlo;
    size_t offhi = (size_t)b*CHW1 + Yhi*256 + Xhi;
    float* ob = out + (size_t)side*HALF_OUT;
    #pragma unroll
    for (int nf = 0; nf < 8; nf++)
        #pragma unroll
        for (int e = 0; e < 2; e++) {
            size_t go = (size_t)(8*nf + 2*q4 + e) * HW;
            ob[offlo + go] = xbase[offlo + go] + O[nf][e]   * mv_lo;
            ob[offhi + go] = xbase[offhi + go] + O[nf][2+e] * mv_hi;
        }
}

// ------------------ launch ------------------
extern "C" void kernel_launch(void* const* d_in, const int* in_sizes, int n_in,
                              void* d_out, int out_size)
{
    (void)in_sizes; (void)n_in; (void)out_size;
    const float* x_left  = (const float*)d_in[0];
    const float* x_right = (const float*)d_in[1];
    const float* cat_l   = (const float*)d_in[2];
    const float* cat_r   = (const float*)d_in[3];
    const int*   d_left  = (const int*)d_in[4];
    const int*   d_right = (const int*)d_in[5];
    const float* gamma   = (const float*)d_in[6];
    const float* beta    = (const float*)d_in[7];
    const float* rb_w1   = (const float*)d_in[8];
    const float* rb_b1   = (const float*)d_in[9];
    const float* rb_w2   = (const float*)d_in[10];
    const float* rb_b2   = (const float*)d_in[11];
    const float* bq_w    = (const float*)d_in[12];
    const float* bq_b    = (const float*)d_in[13];
    const float* bs_w    = (const float*)d_in[14];
    const float* bs_b    = (const float*)d_in[15];
    float* out = (float*)d_out;

    bn_stats_kernel<<<256, 256>>>(cat_l, gamma, beta, 0);
    bn_stats_kernel<<<256, 256>>>(cat_r, gamma, beta, 1);
    prep_w_kernel<<<dim3(16, 2), 256>>>(rb_w1, rb_w2);

    dim3 cgrid(256, 4, 4);   // 128 y-tiles x 2 x-halves, 4 groups, z = side*2+b
    conv1_kernel    <<<cgrid, 512>>>(cat_l, cat_r, rb_b1);
    conv2proj_kernel<<<cgrid, 512>>>(cat_l, cat_r, rb_b2, bq_w, bs_w, bq_b, bs_b);

    dim3 ggrid(4, 256, 2);
    gather_kernel<<<ggrid, 256>>>(nullptr, d_right, 0, 0, 0);  // G_Q  = gather(Q, l2r)
    gather_kernel<<<ggrid, 256>>>(nullptr, d_left,  1, 1, 1);  // G_K  = gather(K, r2l)
    gather_kernel<<<ggrid, 256>>>(x_right, d_left,  1, 2, 2);  // G_XR = gather(x_right, r2l)
    gather_kernel<<<ggrid, 256>>>(x_left,  d_right, 0, 2, 3);  // G_XL = gather(x_left, l2r)

    attn_kernel<<<dim3(1024, 2, 2), 128>>>(x_left, x_right, d_left, d_right, out);
}

// round 8
// speedup vs baseline: 3.0646x; 1.0117x over previous
#include <cuda_runtime.h>
#include <cuda_fp16.h>
#include <cstdint>

// Shapes: B=2, C=64, 4C=256, H=W=256, WS=8, hn=wn=32, P=64, DMAX=48
#define HW    65536
#define CHW4  16777216   // 256*65536
#define CHW1  4194304    // 64*65536
#define HALF_OUT 8388608 // 2*64*65536

// ------------------ device scratch (no runtime allocation) ------------------
// conv1 out, slot-interleaved: word idx = 8 + (z*16+g*4+chunk)*524288 + (y*256+x)*8 + s
__device__ __align__(16) unsigned g_y2[8 + 64L*65536*8];
__device__ float g_Q  [2*64*65536];
__device__ float g_K  [2*64*65536];
__device__ float g_GQ [2*64*65536];    // gather_w(Q, l2r)  flat [b,y,x,c]
__device__ float g_GK [2*64*65536];    // gather_w(K, r2l)
__device__ float g_GXL[2*64*65536];    // gather_w(x_left, l2r)
__device__ float g_GXR[2*64*65536];    // gather_w(x_right, r2l)
__device__ unsigned g_w1h[4*4*4608];   // per (g,chunk): [tap9][oc64][slot8] half2
__device__ unsigned g_w2h[4*4*4608];
__device__ float g_aff[4][256];        // [0]=aL [1]=bL [2]=aR [3]=bR

__device__ __forceinline__ unsigned h2bits(float lo, float hi) {
    __half2 h = __floats2half2_rn(lo, hi);
    return *(unsigned*)&h;
}

#define MMA_F16(d, A0, A1, B)                                               \
    asm volatile("mma.sync.aligned.m16n8k16.row.col.f32.f16.f16.f32 "       \
        "{%0,%1,%2,%3}, {%4,%5,%6,%7}, {%8,%9}, {%0,%1,%2,%3};"             \
        : "+f"((d)[0]), "+f"((d)[1]), "+f"((d)[2]), "+f"((d)[3])            \
        : "r"((A0).x), "r"((A1).x), "r"((A0).y), "r"((A1).y),               \
          "r"((B).x), "r"((B).y))
#define MMA_F16S(d, a0, a1, a2, a3, b0, b1)                                 \
    asm volatile("mma.sync.aligned.m16n8k16.row.col.f32.f16.f16.f32 "       \
        "{%0,%1,%2,%3}, {%4,%5,%6,%7}, {%8,%9}, {%0,%1,%2,%3};"             \
        : "+f"((d)[0]), "+f"((d)[1]), "+f"((d)[2]), "+f"((d)[3])            \
        : "r"(a0), "r"(a1), "r"(a2), "r"(a3), "r"(b0), "r"(b1))

// ------------------ BN batch stats ------------------
__global__ void bn_stats_kernel(const float* __restrict__ cat,
                                const float* __restrict__ gamma,
                                const float* __restrict__ beta, int side)
{
    int ch = blockIdx.x, tid = threadIdx.x;
    const float* p0 = cat + (size_t)ch * HW;
    const float* p1 = cat + (size_t)CHW4 + (size_t)ch * HW;
    double s = 0.0, sq = 0.0;
    for (int e = tid; e < HW; e += 256) {
        float v0 = p0[e], v1 = p1[e];
        s  += (double)v0 + (double)v1;
        sq += (double)v0 * v0 + (double)v1 * v1;
    }
    __shared__ double sh_s[256], sh_q[256];
    sh_s[tid] = s; sh_q[tid] = sq;
    __syncthreads();
    for (int st = 128; st > 0; st >>= 1) {
        if (tid < st) { sh_s[tid] += sh_s[tid+st]; sh_q[tid] += sh_q[tid+st]; }
        __syncthreads();
    }
    if (tid == 0) {
        double n = 131072.0;
        double mu  = sh_s[0] / n;
        double var = sh_q[0] / n - mu * mu;
        float a = gamma[ch] * rsqrtf((float)var + 1e-5f);
        g_aff[side*2][ch]   = a;
        g_aff[side*2+1][ch] = beta[ch] - a * (float)mu;
    }
}

// ------------------ weight prep ------------------
__global__ void prep_w_kernel(const float* __restrict__ w1, const float* __restrict__ w2)
{
    int gc = blockIdx.x;            // g*4 + chunk
    int layer = blockIdx.y;
    const float* w = layer ? w2 : w1;
    unsigned* dst = (layer ? g_w2h : g_w1h) + gc * 4608;
    int g = gc >> 2, chunk = gc & 3;
    for (int e = threadIdx.x; e < 4608; e += 256) {
        int tap = e >> 9, oc = (e >> 3) & 63, s = e & 7;
        int p = (s >> 1) + 4*(s & 1);
        int ic = chunk*16 + 2*p;
        int o = g*64 + oc;
        dst[e] = h2bits(w[(o*64 + ic)*9 + tap], w[(o*64 + ic + 1)*9 + tap]);
    }
}

// ------------------ MMA tap loop: 2mf x 8nf per warp ------------------
__device__ __forceinline__ void mma_taps(const unsigned* sIn, const unsigned* sW,
    int wset, int wrow, int wx, int r4, int c4, float acc[2][8][4])
{
    #pragma unroll
    for (int tap = 0; tap < 9; tap++) {
        const int dy = tap / 3, dx = tap - dy*3;
        const unsigned* wB = sW + tap*512;
        uint2 A0[2], A1[2];
        #pragma unroll
        for (int mf = 0; mf < 2; mf++) {
            int oc0 = wset*32 + mf*16 + r4;
            A0[mf] = *(const uint2*)(wB + oc0*8 + 2*c4);
            A1[mf] = *(const uint2*)(wB + (oc0 + 8)*8 + 2*c4);
        }
        const unsigned* bp = sIn + (wrow + dy)*1064 + (wx + dx + r4)*8 + 2*c4;
        #pragma unroll
        for (int nf = 0; nf < 8; nf++) {
            uint2 Bf = *(const uint2*)(bp + nf*64);
            MMA_F16(acc[0][nf], A0[0], A1[0], Bf);
            MMA_F16(acc[1][nf], A0[1], A1[1], Bf);
        }
    }
}

// ------------------ conv1: slot-interleaved fp16 out ------------------
__global__ __launch_bounds__(256, 2) void conv1_kernel(
    const float* __restrict__ cat_l, const float* __restrict__ cat_r,
    const float* __restrict__ b1)
{
    __shared__ __align__(16) unsigned sm[8864];   // sIn 4256 + sW 4608
    unsigned* sIn = sm;
    unsigned* sW  = sm + 4256;
    int tile = blockIdx.x, g = blockIdx.y, z = blockIdx.z;
    int side = z >> 1, b = z & 1;
    int y0 = (tile >> 1) * 2, x0 = (tile & 1) * 128;
    int tid = threadIdx.x, lane = tid & 31, warp = tid >> 5;
    int wset = warp >> 2, w4 = warp & 3, wrow = w4 >> 1, wx = (w4 & 1) * 64;
    int r4 = lane >> 2, c4 = lane & 3;

    float acc[2][8][4];
    #pragma unroll
    for (int m = 0; m < 2; m++)
        #pragma unroll
        for (int n = 0; n < 8; n++)
            #pragma unroll
            for (int k = 0; k < 4; k++) acc[m][n][k] = 0.f;

    const float* cat = side ? cat_r : cat_l;
    const float* fin = cat + (size_t)b*CHW4 + (size_t)(g*64)*HW;
    const float* a_bn = g_aff[side*2] + g*64;
    const float* b_bn = g_aff[side*2+1] + g*64;
    const unsigned* wImg = g_w1h + g*4*4608;

    #pragma unroll 1
    for (int chunk = 0; chunk < 4; chunk++) {
        {
            const float4* src = (const float4*)(wImg + chunk*4608);
            float4* d4 = (float4*)sW;
            for (int e = tid; e < 1152; e += 256) d4[e] = src[e];
        }
        for (int it = tid; it < 1024; it += 256) {
            int p = it & 7, pl = (it >> 3) & 3, j = it >> 5;
            int s = (p < 4) ? 2*p : 2*p - 7;
            int yy = y0 + pl - 1;
            int icA = chunk*16 + 2*p;
            unsigned o0, o1, o2, o3;
            if ((unsigned)yy < 256u) {
                const float* pa = fin + (size_t)icA*HW + yy*256 + x0 + 4*j;
                float4 a = *(const float4*)pa;
                float4 bq = *(const float4*)(pa + HW);
                float ka = a_bn[icA], ba = b_bn[icA];
                float kb = a_bn[icA+1], bb = b_bn[icA+1];
                a.x = fmaf(ka,a.x,ba); a.y = fmaf(ka,a.y,ba);
                a.z = fmaf(ka,a.z,ba); a.w = fmaf(ka,a.w,ba);
                bq.x = fmaf(kb,bq.x,bb); bq.y = fmaf(kb,bq.y,bb);
                bq.z = fmaf(kb,bq.z,bb); bq.w = fmaf(kb,bq.w,bb);
                o0 = h2bits(a.x, bq.x); o1 = h2bits(a.y, bq.y);
                o2 = h2bits(a.z, bq.z); o3 = h2bits(a.w, bq.w);
            } else { o0 = o1 = o2 = o3 = 0u; }
            int base = pl*1064 + (4*j + 1)*8 + s;
            sIn[base] = o0; sIn[base+8] = o1; sIn[base+16] = o2; sIn[base+24] = o3;
        }
        if (tid < 64) {
            int p = tid >> 3, pl = (tid >> 1) & 3, right = tid & 1;
            int s = (p < 4) ? 2*p : 2*p - 7;
            int yy = y0 + pl - 1;
            int xx = right ? x0 + 128 : x0 - 1;
            int col = right ? 129 : 0;
            int icA = chunk*16 + 2*p;
            unsigned o = 0u;
            if ((unsigned)yy < 256u && (unsigned)xx < 256u) {
                size_t off = (size_t)icA*HW + yy*256 + xx;
                float lo = fin[off], hi = fin[off + HW];
                lo = fmaf(a_bn[icA], lo, b_bn[icA]);
                hi = fmaf(a_bn[icA+1], hi, b_bn[icA+1]);
                o = h2bits(lo, hi);
            }
            sIn[pl*1064 + col*8 + s] = o;
        }
        __syncthreads();
        mma_taps(sIn, sW, wset, wrow, wx, r4, c4, acc);
        __syncthreads();
    }

    // epilogue: bias + leaky + channel-pair shfl -> slot-interleaved store
    const float* b1g = b1 + g*64;
    size_t pxrow = ((size_t)(y0 + wrow)*256 + x0 + wx);
    #pragma unroll
    for (int mf = 0; mf < 2; mf++) {
        int oc = wset*32 + mf*16 + r4;
        float bv0 = b1g[oc], bv1 = b1g[oc + 8];
        int chunkc = wset*2 + mf;
        unsigned* cb = g_y2 + 8 + (size_t)((z*4 + g)*4 + chunkc)*524288 + pxrow*8 + r4;
        #pragma unroll
        for (int nf = 0; nf < 8; nf++) {
            float v0 = acc[mf][nf][0] + bv0; v0 = (v0 > 0.f) ? v0 : 0.1f*v0;
            float v1 = acc[mf][nf][1] + bv0; v1 = (v1 > 0.f) ? v1 : 0.1f*v1;
            float v2 = acc[mf][nf][2] + bv1; v2 = (v2 > 0.f) ? v2 : 0.1f*v2;
            float v3 = acc[mf][nf][3] + bv1; v3 = (v3 > 0.f) ? v3 : 0.1f*v3;
            float pv0 = __shfl_xor_sync(~0u, v0, 4);
            float pv1 = __shfl_xor_sync(~0u, v1, 4);
            float pv2 = __shfl_xor_sync(~0u, v2, 4);
            float pv3 = __shfl_xor_sync(~0u, v3, 4);
            unsigned* wp = cb + (nf*8 + 2*c4)*8;
            if ((r4 & 1) == 0) { wp[0] = h2bits(v0, pv0); wp[8] = h2bits(v1, pv1); }
            else               { wp[0] = h2bits(pv2, v2); wp[8] = h2bits(pv3, v3); }
        }
    }
}

// ------------------ conv2 + residual + grouped 1x1 projection ------------------
__global__ __launch_bounds__(256, 2) void conv2proj_kernel(
    const float* __restrict__ cat_l, const float* __restrict__ cat_r,
    const float* __restrict__ b2,
    const float* __restrict__ bq_w, const float* __restrict__ bs_w,
    const float* __restrict__ bq_b, const float* __restrict__ bs_b)
{
    __shared__ __align__(16) unsigned sm[9728];   // conv: sIn 4256 + sW 4608; epi: resbh 9216 + pwh 512
    unsigned* sIn = sm;
    unsigned* sW  = sm + 4256;
    int tile = blockIdx.x, g = blockIdx.y, z = blockIdx.z;
    int side = z >> 1, b = z & 1;
    int y0 = (tile >> 1) * 2, x0 = (tile & 1) * 128;
    int tid = threadIdx.x, lane = tid & 31, warp = tid >> 5;
    int wset = warp >> 2, w4 = warp & 3, wrow = w4 >> 1, wx = (w4 & 1) * 64;
    int r4 = lane >> 2, c4 = lane & 3;

    float acc[2][8][4];
    #pragma unroll
    for (int m = 0; m < 2; m++)
        #pragma unroll
        for (int n = 0; n < 8; n++)
            #pragma unroll
            for (int k = 0; k < 4; k++) acc[m][n][k] = 0.f;

    const unsigned* wImg = g_w2h + g*4*4608;
    int clo = (x0 == 0) ? 1 : 0;
    int chi = (x0 == 0) ? 130 : 129;

    #pragma unroll 1
    for (int chunk = 0; chunk < 4; chunk++) {
        {
            const float4* src = (const float4*)(wImg + chunk*4608);
            float4* d4 = (float4*)sW;
            for (int e = tid; e < 1152; e += 256) d4[e] = src[e];
        }
        // contiguous halo-inclusive copy from slot-interleaved g_y2
        {
            const unsigned* src = g_y2 + 8 + (size_t)((z*4 + g)*4 + chunk)*524288;
            int pl = tid >> 6, lt = tid & 63;
            int yy = y0 + pl - 1;
            bool rowok = (unsigned)yy < 256u;
            const float4* s4 = (const float4*)(src + ((size_t)yy*256 + x0 - 1)*8);
            float4* d4 = (float4*)(sIn + pl*1064);
            for (int f = lt; f < 260; f += 64) {
                int col = f >> 1;
                float4 v = make_float4(0.f, 0.f, 0.f, 0.f);
                if (rowok && col >= clo && col < chi) v = s4[f];
                d4[f] = v;
            }
        }
        __syncthreads();
        mma_taps(sIn, sW, wset, wrow, wx, r4, c4, acc);
        __syncthreads();
    }

    // ---- epilogue: resb = conv2 + b2 + bn(cat) (fp16) -> 1x1 projection mma
    __half* resbh = (__half*)sm;              // [256 px][72 halves]
    unsigned* pwh = sm + 9216;                // [16 oc][32 slot words]
    const float* cat = side ? cat_r : cat_l;
    const float* a_bn = g_aff[side*2] + g*64;
    const float* b_bn = g_aff[side*2+1] + g*64;
    const float* b2g = b2 + g*64;
    const float* pbg = (side ? bs_b : bq_b) + g*16;
    float* qout = (side ? g_K : g_Q) + (size_t)b*CHW1 + (size_t)(g*16)*HW;

    {
        const float* pwsrc = (side ? bs_w : bq_w) + (size_t)(g*16)*64;
        for (int e = tid; e < 512; e += 256) {
            int oc = e >> 5, w5 = e & 31;
            int kc = w5 >> 3, s = w5 & 7;
            int p = (s >> 1) + 4*(s & 1);
            int ic0 = kc*16 + 2*p;
            pwh[e] = h2bits(pwsrc[oc*64 + ic0], pwsrc[oc*64 + ic0 + 1]);
        }
    }
    {
        const float* catb = cat + (size_t)b*CHW4 + (size_t)(g*64)*HW
                          + (size_t)(y0 + wrow)*256 + x0;
        #pragma unroll
        for (int mf = 0; mf < 2; mf++) {
            int ch = wset*32 + mf*16 + r4;
            float bv0 = b2g[ch], bv1 = b2g[ch + 8];
            float a0c = a_bn[ch], b0c = b_bn[ch];
            float a1c = a_bn[ch+8], b1c = b_bn[ch+8];
            #pragma unroll
            for (int nf = 0; nf < 8; nf++) {
                int px = wx + nf*8 + 2*c4;
                int pxl = wrow*128 + px;
                float2 cv0 = *(const float2*)&catb[(size_t)ch*HW + px];
                float2 cv1 = *(const float2*)&catb[(size_t)(ch+8)*HW + px];
                resbh[pxl*72 + ch]       = __float2half_rn(acc[mf][nf][0] + bv0 + fmaf(a0c, cv0.x, b0c));
                resbh[(pxl+1)*72 + ch]   = __float2half_rn(acc[mf][nf][1] + bv0 + fmaf(a0c, cv0.y, b0c));
                resbh[pxl*72 + ch+8]     = __float2half_rn(acc[mf][nf][2] + bv1 + fmaf(a1c, cv1.x, b1c));
                resbh[(pxl+1)*72 + ch+8] = __float2half_rn(acc[mf][nf][3] + bv1 + fmaf(a1c, cv1.y, b1c));
            }
        }
    }
    __syncthreads();
    #pragma unroll
    for (int sb = 0; sb < 2; sb++) {
        int pm = warp*32 + sb*16;
        float PA[2][4];
        #pragma unroll
        for (int nf = 0; nf < 2; nf++) {
            float p0 = pbg[8*nf + 2*c4], p1 = pbg[8*nf + 2*c4 + 1];
            PA[nf][0] = p0; PA[nf][1] = p1; PA[nf][2] = p0; PA[nf][3] = p1;
        }
        #pragma unroll
        for (int kc = 0; kc < 4; kc++) {
            unsigned a0 = *(const unsigned*)&resbh[(pm + r4)*72 + kc*16 + 2*c4];
            unsigned a2 = *(const unsigned*)&resbh[(pm + r4)*72 + kc*16 + 2*c4 + 8];
            unsigned a1 = *(const unsigned*)&resbh[(pm + r4 + 8)*72 + kc*16 + 2*c4];
            unsigned a3 = *(const unsigned*)&resbh[(pm + r4 + 8)*72 + kc*16 + 2*c4 + 8];
            #pragma unroll
            for (int nf = 0; nf < 2; nf++) {
                uint2 bb = *(const uint2*)&pwh[(nf*8 + r4)*32 + kc*8 + 2*c4];
                MMA_F16S(PA[nf], a0, a1, a2, a3, bb.x, bb.y);
            }
        }
        #pragma unroll
        for (int nf = 0; nf < 2; nf++)
            #pragma unroll
            for (int e = 0; e < 2; e++) {
                int oc = 8*nf + 2*c4 + e;
                int pxa = pm + r4, pxb = pxa + 8;
                qout[(size_t)oc*HW + (size_t)(y0 + (pxa >> 7))*256 + x0 + (pxa & 127)] = PA[nf][e];
                qout[(size_t)oc*HW + (size_t)(y0 + (pxb >> 7))*256 + x0 + (pxb & 127)] = PA[nf][2+e];
            }
    }
}

// ------------------ transpose-gather ------------------
__global__ __launch_bounds__(256) void gather_kernel(
    const float* __restrict__ srcParam, const int* __restrict__ dvals,
    int mode, int srcSel, int dstSel)
{
    __shared__ float s[64][113];
    int x0 = blockIdx.x * 64;
    int y  = blockIdx.y;
    int b  = blockIdx.z;
    const float* src = (srcSel == 0) ? g_Q : (srcSel == 1) ? g_K : srcParam;
    float* dst = (dstSel == 0) ? g_GQ : (dstSel == 1) ? g_GK :
                 (dstSel == 2) ? g_GXR : g_GXL;
    int lo = (mode == 0) ? x0 : max(x0 - 48, 0);
    int t = threadIdx.x;
    const float* sbp = src + (size_t)b*CHW1 + y*256;
    for (int e = t; e < 64*112; e += 256) {
        int c = e / 112, j = e - c*112;
        int col = min(lo + j, 255);
        s[c][j] = sbp[(size_t)c*HW + col];
    }
    __syncthreads();
    float* db = dst + (size_t)b*CHW1 + y*16384 + x0*64;
    const int* dp = dvals + b*HW + y*256;
    for (int e = t; e < 4096; e += 256) {
        int xi = e >> 6, c = e & 63;
        int x = x0 + xi;
        int d = dp[x];
        int sc = (mode == 0) ? min(x + d, 255) : max(x - d, 0);
        db[xi*64 + c] = s[c][sc - lo];
    }
}

// ------------------ per-window attention (fp16 mma) + output assembly ------------------
__global__ __launch_bounds__(128) void attn_kernel(
    const float* __restrict__ xl, const float* __restrict__ xr,
    const int* __restrict__ dl, const int* __restrict__ dr,
    float* __restrict__ out)
{
    __shared__ float sRaw[64][68];
    __shared__ __align__(16) unsigned sA[2048];
    __shared__ __align__(16) unsigned sB[2048];
    __shared__ float mu[8];
    int win = blockIdx.x, side = blockIdx.y, b = blockIdx.z;
    int hi = win >> 5, wi = win & 31;
    int t = threadIdx.x, lane = t & 31, warp = t >> 5;
    int q4 = lane & 3, r4 = lane >> 2;

    const float *Ab, *Bb, *Xb;
    if (side == 0) { Ab = g_Q; Bb = g_GK; Xb = g_GXR; }
    else           { Ab = g_K; Bb = g_GQ; Xb = g_GXL; }
    size_t base = (size_t)b*CHW1 + (size_t)(hi*8)*256 + wi*8;

    for (int e = t; e < 4096; e += 128) {
        int j = e & 63, c = e >> 6;
        sRaw[j][c] = Ab[base + (size_t)c*HW + ((j >> 3)*256 + (j & 7))];
    }
    __syncthreads();
    for (int e = t; e < 2048; e += 128) {
        int i = e >> 5, w5 = e & 31;
        int kc = w5 >> 3, s = w5 & 7;
        int p = (s >> 1) + 4*(s & 1);
        int c0 = kc*16 + 2*p;
        sA[e] = h2bits(sRaw[i][c0], sRaw[i][c0+1]);
    }
    __syncthreads();
    for (int e = t; e < 4096; e += 128) {
        int j = e & 63, c = e >> 6;
        sRaw[j][c] = Bb[base + (size_t)c*HW + ((j >> 3)*256 + (j & 7))];
    }
    __syncthreads();
    {
        int p = t >> 4, sub = t & 15;
        float s = 0.f;
        #pragma unroll 4
        for (int m = 0; m < 32; m++) {
            int el = sub*32 + m;
            s += sRaw[8*p + (el >> 6)][el & 63];
        }
        s += __shfl_xor_sync(~0u, s, 8);
        s += __shfl_xor_sync(~0u, s, 4);
        s += __shfl_xor_sync(~0u, s, 2);
        s += __shfl_xor_sync(~0u, s, 1);
        if (sub == 0) mu[p] = s * (1.f/512.f);
    }
    __syncthreads();
    for (int e = t; e < 2048; e += 128) {
        int j = e >> 5, w5 = e & 31;
        int kc = w5 >> 3, s = w5 & 7;
        int p = (s >> 1) + 4*(s & 1);
        int c0 = kc*16 + 2*p;
        float m = mu[j >> 3];
        sB[e] = h2bits(sRaw[j][c0] - m, sRaw[j][c0+1] - m);
    }
    __syncthreads();

    int m0 = warp * 16;
    float S[8][4];
    #pragma unroll
    for (int nf = 0; nf < 8; nf++)
        #pragma unroll
        for (int k = 0; k < 4; k++) S[nf][k] = 0.f;
    #pragma unroll
    for (int kc = 0; kc < 4; kc++) {
        uint2 alo = *(const uint2*)&sA[(m0 + r4)*32 + kc*8 + q4*2];
        uint2 ahi = *(const uint2*)&sA[(m0 + r4 + 8)*32 + kc*8 + q4*2];
        #pragma unroll
        for (int nf = 0; nf < 8; nf++) {
            uint2 bb = *(const uint2*)&sB[(nf*8 + r4)*32 + kc*8 + q4*2];
            MMA_F16S(S[nf], alo.x, ahi.x, alo.y, ahi.y, bb.x, bb.y);
        }
    }
    float mlo = -1e30f, mhi = -1e30f;
    #pragma unroll
    for (int nf = 0; nf < 8; nf++) {
        mlo = fmaxf(mlo, fmaxf(S[nf][0], S[nf][1]));
        mhi = fmaxf(mhi, fmaxf(S[nf][2], S[nf][3]));
    }
    mlo = fmaxf(mlo, __shfl_xor_sync(~0u, mlo, 1));
    mlo = fmaxf(mlo, __shfl_xor_sync(~0u, mlo, 2));
    mhi = fmaxf(mhi, __shfl_xor_sync(~0u, mhi, 1));
    mhi = fmaxf(mhi, __shfl_xor_sync(~0u, mhi, 2));
    float slo = 0.f, shi = 0.f;
    #pragma unroll
    for (int nf = 0; nf < 8; nf++) {
        S[nf][0] = __expf(S[nf][0] - mlo); S[nf][1] = __expf(S[nf][1] - mlo);
        S[nf][2] = __expf(S[nf][2] - mhi); S[nf][3] = __expf(S[nf][3] - mhi);
        slo += S[nf][0] + S[nf][1];
        shi += S[nf][2] + S[nf][3];
    }
    slo += __shfl_xor_sync(~0u, slo, 1);
    slo += __shfl_xor_sync(~0u, slo, 2);
    shi += __shfl_xor_sync(~0u, shi, 1);
    shi += __shfl_xor_sync(~0u, shi, 2);
    float invlo = 1.f / slo, invhi = 1.f / shi;
    unsigned pa[4][4];
    #pragma unroll
    for (int kc = 0; kc < 4; kc++) {
        pa[kc][0] = h2bits(S[2*kc][0]*invlo,   S[2*kc][1]*invlo);
        pa[kc][1] = h2bits(S[2*kc][2]*invhi,   S[2*kc][3]*invhi);
        pa[kc][2] = h2bits(S[2*kc+1][0]*invlo, S[2*kc+1][1]*invlo);
        pa[kc][3] = h2bits(S[2*kc+1][2]*invhi, S[2*kc+1][3]*invhi);
    }
    __syncthreads();

    for (int e = t; e < 4096; e += 128) {
        int j = e & 63, c = e >> 6;
        sRaw[j][c] = Xb[base + (size_t)c*HW + ((j >> 3)*256 + (j & 7))];
    }
    __syncthreads();
    for (int e = t; e < 2048; e += 128) {
        int c = e >> 5, w5 = e & 31;
        int kc = w5 >> 3, s = w5 & 7;
        int p = (s >> 1) + 4*(s & 1);
        int j0 = kc*16 + 2*p;
        sB[e] = h2bits(sRaw[j0][c], sRaw[j0+1][c]);
    }
    __syncthreads();
    float O[8][4];
    #pragma unroll
    for (int nf = 0; nf < 8; nf++)
        #pragma unroll
        for (int k = 0; k < 4; k++) O[nf][k] = 0.f;
    #pragma unroll
    for (int kc = 0; kc < 4; kc++) {
        #pragma unroll
        for (int nf = 0; nf < 8; nf++) {
            uint2 bb = *(const uint2*)&sB[(nf*8 + r4)*32 + kc*8 + q4*2];
            MMA_F16S(O[nf], pa[kc][0], pa[kc][1], pa[kc][2], pa[kc][3], bb.x, bb.y);
        }
    }
    int ilo = m0 + r4, ihi = ilo + 8;
    int Ylo = hi*8 + (ilo >> 3), Xlo = wi*8 + (ilo & 7);
    int Yhi = hi*8 + (ihi >> 3), Xhi = wi*8 + (ihi & 7);
    const float* xbase = side ? xr : xl;
    float mv_lo, mv_hi;
    if (side == 0) {
        mv_lo = (Xlo - dl[b*HW + Ylo*256 + Xlo] >= 0) ? 1.f : 0.f;
        mv_hi = (Xhi - dl[b*HW + Yhi*256 + Xhi] >= 0) ? 1.f : 0.f;
    } else {
        mv_lo = (Xlo + dr[b*HW + Ylo*256 + Xlo] <= 255) ? 1.f : 0.f;
        mv_hi = (Xhi + dr[b*HW + Yhi*256 + Xhi] <= 255) ? 1.f : 0.f;
    }
    size_t offlo = (size_t)b*CHW1 + Ylo*256 + Xlo;
    size_t offhi = (size_t)b*CHW1 + Yhi*256 + Xhi;
    float* ob = out + (size_t)side*HALF_OUT;
    #pragma unroll
    for (int nf = 0; nf < 8; nf++)
        #pragma unroll
        for (int e = 0; e < 2; e++) {
            size_t go = (size_t)(8*nf + 2*q4 + e) * HW;
            ob[offlo + go] = xbase[offlo + go] + O[nf][e]   * mv_lo;
            ob[offhi + go] = xbase[offhi + go] + O[nf][2+e] * mv_hi;
        }
}

// ------------------ launch ------------------
extern "C" void kernel_launch(void* const* d_in, const int* in_sizes, int n_in,
                              void* d_out, int out_size)
{
    (void)in_sizes; (void)n_in; (void)out_size;
    const float* x_left  = (const float*)d_in[0];
    const float* x_right = (const float*)d_in[1];
    const float* cat_l   = (const float*)d_in[2];
    const float* cat_r   = (const float*)d_in[3];
    const int*   d_left  = (const int*)d_in[4];
    const int*   d_right = (const int*)d_in[5];
    const float* gamma   = (const float*)d_in[6];
    const float* beta    = (const float*)d_in[7];
    const float* rb_w1   = (const float*)d_in[8];
    const float* rb_b1   = (const float*)d_in[9];
    const float* rb_w2   = (const float*)d_in[10];
    const float* rb_b2   = (const float*)d_in[11];
    const float* bq_w    = (const float*)d_in[12];
    const float* bq_b    = (const float*)d_in[13];
    const float* bs_w    = (const float*)d_in[14];
    const float* bs_b    = (const float*)d_in[15];
    float* out = (float*)d_out;

    bn_stats_kernel<<<256, 256>>>(cat_l, gamma, beta, 0);
    bn_stats_kernel<<<256, 256>>>(cat_r, gamma, beta, 1);
    prep_w_kernel<<<dim3(16, 2), 256>>>(rb_w1, rb_w2);

    dim3 cgrid(256, 4, 4);   // 128 y-tiles x 2 x-halves, 4 groups, z = side*2+b
    conv1_kernel    <<<cgrid, 256>>>(cat_l, cat_r, rb_b1);
    conv2proj_kernel<<<cgrid, 256>>>(cat_l, cat_r, rb_b2, bq_w, bs_w, bq_b, bs_b);

    dim3 ggrid(4, 256, 2);
    gather_kernel<<<ggrid, 256>>>(nullptr, d_right, 0, 0, 0);  // G_Q  = gather(Q, l2r)
    gather_kernel<<<ggrid, 256>>>(nullptr, d_left,  1, 1, 1);  // G_K  = gather(K, r2l)
    gather_kernel<<<ggrid, 256>>>(x_right, d_left,  1, 2, 2);  // G_XR = gather(x_right, r2l)
    gather_kernel<<<ggrid, 256>>>(x_left,  d_right, 0, 2, 3);  // G_XL = gather(x_left, l2r)

    attn_kernel<<<dim3(1024, 2, 2), 128>>>(x_left, x_right, d_left, d_right, out);
}